// round 5
// baseline (speedup 1.0000x reference)
#include <cuda_runtime.h>
#include <math.h>

#define NNODES 50000
#define NEDGES 400000
#define HEADS  4

typedef unsigned long long ull;

// ---------------- scratch (device globals; no allocation allowed) -------------
__device__ float g_Wx  [NNODES * 512];
__device__ float g_bufA[NNODES * 256];
__device__ float g_bufB[NNODES * 256];
__device__ float g_ssrc[NNODES * HEADS];
__device__ float g_sdst[NNODES * HEADS];
__device__ int g_cnt   [NNODES];
__device__ int g_rowptr[NNODES + 1];
__device__ int g_fill  [NNODES];
__device__ int g_srcs  [NEDGES];

// ---------------- SGEMM, FFMA2, 128x256 tile, 8x16 micro ----------------------
#define BM 128
#define BN 256
#define BK 8
#define TM 8
#define TN 16

__device__ __forceinline__ ull pack_dup(float x) {
    ull r;
    asm("mov.b64 %0, {%1, %1};" : "=l"(r) : "f"(x));
    return r;
}
__device__ __forceinline__ void ffma2(ull& d, ull a, ull b) {
    asm("fma.rn.f32x2 %0, %1, %2, %0;" : "+l"(d) : "l"(a), "l"(b));
}

__global__ __launch_bounds__(256, 1)
void sgemm_kernel(const float* __restrict__ A, const float* __restrict__ B,
                  float* __restrict__ C, int M, int N, int K)
{
    __shared__ float As[2][BK][BM];
    __shared__ float Bs[2][BK][BN];

    const int tid = threadIdx.x;
    const int block_row = blockIdx.y * BM;
    const int block_col = blockIdx.x * BN;

    const int tx = tid % 16;           // col group: 16 cols each -> 256
    const int ty = tid / 16;           // row group: 8 rows each -> 128

    // A tile: 128x8 = 1024 floats, 4 per thread
    const int a_row = tid >> 1;        // 0..127
    const int a_col = (tid & 1) * 4;   // 0 or 4
    // B tile: 8x256 = 2048 floats, two float4 per thread (cols +0 / +128)
    const int b_row = tid >> 5;        // 0..7
    const int b_col = (tid & 31) * 4;  // 0..124

    const int gr_a = block_row + a_row;

    ull acc2[TM][TN / 2];
#pragma unroll
    for (int i = 0; i < TM; i++)
#pragma unroll
        for (int j = 0; j < TN / 2; j++) acc2[i][j] = 0ull;

    // ---- preload tile 0 ----
    {
#pragma unroll
        for (int i = 0; i < 4; i++) {
            const int gc = a_col + i;
            float v = 0.0f;
            if (gr_a < M && gc < K) v = A[(long long)gr_a * K + gc];
            As[0][a_col + i][a_row] = v;
        }
        float4 v0 = make_float4(0.f, 0.f, 0.f, 0.f);
        float4 v1 = v0;
        if (b_row < K) {
            const float* brow = &B[(long long)b_row * N + block_col];
            v0 = *(const float4*)&brow[b_col];
            v1 = *(const float4*)&brow[b_col + 128];
        }
        *(float4*)&Bs[0][b_row][b_col]       = v0;
        *(float4*)&Bs[0][b_row][b_col + 128] = v1;
    }
    __syncthreads();

    int buf = 0;
    for (int k0 = 0; k0 < K; k0 += BK) {
        const int kn = k0 + BK;
        const bool more = kn < K;

        // register prefetch of next tile
        float pa[4];
        float4 pb0 = make_float4(0.f, 0.f, 0.f, 0.f), pb1 = pb0;
        if (more) {
#pragma unroll
            for (int i = 0; i < 4; i++) {
                const int gc = kn + a_col + i;
                pa[i] = 0.0f;
                if (gr_a < M && gc < K) pa[i] = A[(long long)gr_a * K + gc];
            }
            const int gk = kn + b_row;
            if (gk < K) {
                const float* brow = &B[(long long)gk * N + block_col];
                pb0 = *(const float4*)&brow[b_col];
                pb1 = *(const float4*)&brow[b_col + 128];
            }
        }

        // compute on current buffer
#pragma unroll
        for (int k = 0; k < BK; k++) {
            float ar[TM];
            *(float4*)&ar[0] = *(const float4*)&As[buf][k][ty * TM + 0];
            *(float4*)&ar[4] = *(const float4*)&As[buf][k][ty * TM + 4];
            ull b2[TN / 2];
#pragma unroll
            for (int q = 0; q < 4; q++) {
                const ulonglong2 bv = *(const ulonglong2*)&Bs[buf][k][tx * TN + q * 4];
                b2[q * 2]     = bv.x;
                b2[q * 2 + 1] = bv.y;
            }
#pragma unroll
            for (int i = 0; i < TM; i++) {
                const ull a2 = pack_dup(ar[i]);
#pragma unroll
                for (int j = 0; j < TN / 2; j++)
                    ffma2(acc2[i][j], a2, b2[j]);
            }
        }

        // stage prefetched tile
        if (more) {
#pragma unroll
            for (int i = 0; i < 4; i++)
                As[buf ^ 1][a_col + i][a_row] = pa[i];
            *(float4*)&Bs[buf ^ 1][b_row][b_col]       = pb0;
            *(float4*)&Bs[buf ^ 1][b_row][b_col + 128] = pb1;
        }
        __syncthreads();
        buf ^= 1;
    }

    // store: rows ty*8.., cols tx*16..tx*16+15
#pragma unroll
    for (int i = 0; i < TM; i++) {
        const int gr = block_row + ty * TM + i;
        if (gr < M) {
            float out[TN];
#pragma unroll
            for (int j = 0; j < TN / 2; j++) {
                const float2 f = *(const float2*)&acc2[i][j];
                out[2 * j]     = f.x;
                out[2 * j + 1] = f.y;
            }
            float* c = &C[(long long)gr * N + block_col + tx * TN];
#pragma unroll
            for (int q = 0; q < 4; q++)
                *(float4*)&c[q * 4] = make_float4(out[q * 4], out[q * 4 + 1],
                                                  out[q * 4 + 2], out[q * 4 + 3]);
        }
    }
}

// ---------------- CSR construction (dst-grouped) -------------------------------
__global__ void hist_kernel(const int* __restrict__ dst, int* __restrict__ cnt, int E)
{
    const int e = blockIdx.x * blockDim.x + threadIdx.x;
    if (e < E) atomicAdd(&cnt[dst[e]], 1);
}

__global__ void scan_kernel(const int* __restrict__ cnt, int* __restrict__ rowptr,
                            int* __restrict__ fill, int n)
{
    __shared__ int sh[1024];
    __shared__ int carry;
    if (threadIdx.x == 0) { carry = 0; rowptr[0] = 0; }
    __syncthreads();
    for (int base = 0; base < n; base += 1024) {
        const int i = base + (int)threadIdx.x;
        const int v = (i < n) ? cnt[i] : 0;
        sh[threadIdx.x] = v;
        __syncthreads();
#pragma unroll
        for (int o = 1; o < 1024; o <<= 1) {
            int t = (threadIdx.x >= (unsigned)o) ? sh[threadIdx.x - o] : 0;
            __syncthreads();
            sh[threadIdx.x] += t;
            __syncthreads();
        }
        const int incl = sh[threadIdx.x];
        if (i < n) {
            rowptr[i + 1] = carry + incl;
            fill[i] = carry + incl - v;
        }
        __syncthreads();
        if (threadIdx.x == 0) carry += sh[1023];
        __syncthreads();
    }
}

__global__ void scatter_kernel(const int* __restrict__ src, const int* __restrict__ dst,
                               int* __restrict__ fill, int* __restrict__ srcs, int E)
{
    const int e = blockIdx.x * blockDim.x + threadIdx.x;
    if (e >= E) return;
    const int pos = atomicAdd(&fill[dst[e]], 1);
    srcs[pos] = src[e];
}

// ---------------- per-(node,head) attention scores ----------------------------
__global__ void scores_kernel(const float* __restrict__ Wx,
                              const float* __restrict__ a,
                              float* __restrict__ s_src, float* __restrict__ s_dst,
                              int n, int hd)
{
    const int warp = (blockIdx.x * blockDim.x + threadIdx.x) >> 5;
    const int lane = threadIdx.x & 31;
    if (warp >= n * HEADS) return;
    const int node = warp / HEADS;
    const int h    = warp % HEADS;
    const float* row = Wx + (long long)node * HEADS * hd + h * hd;
    float ss = 0.f, sd = 0.f;
    for (int d = lane; d < hd; d += 32) {
        const float v = row[d];
        ss = fmaf(v, a[d], ss);
        sd = fmaf(v, a[hd + d], sd);
    }
#pragma unroll
    for (int o = 16; o; o >>= 1) {
        ss += __shfl_xor_sync(0xffffffffu, ss, o);
        sd += __shfl_xor_sync(0xffffffffu, sd, o);
    }
    if (lane == 0) {
        s_src[node * HEADS + h] = ss;
        s_dst[node * HEADS + h] = sd;
    }
}

// ------ fused edge-softmax + weighted aggregation + ELU + LayerNorm -----------
template <int DOUT>
__global__ __launch_bounds__(256)
void gat_aggregate_ln_kernel(const int* __restrict__ rowptr,
                             const int* __restrict__ srcs,
                             const float* __restrict__ ssrc,
                             const float* __restrict__ sdst,
                             const float* __restrict__ Wx,
                             const float* __restrict__ g,
                             const float* __restrict__ b,
                             float* __restrict__ out, int n)
{
    const int warp = (blockIdx.x * blockDim.x + threadIdx.x) >> 5;
    const int lane = threadIdx.x & 31;
    if (warp >= n) return;
    const int node = warp;
    const int begin = rowptr[node];
    const int end   = rowptr[node + 1];

    constexpr int PER = DOUT / 32;
    const int h = lane >> 3;

    const float4 sdv = *(const float4*)&sdst[node * 4];
    const float sd0 = sdv.x, sd1 = sdv.y, sd2 = sdv.z, sd3 = sdv.w;

    float d0 = 0.f, d1 = 0.f, d2 = 0.f, d3 = 0.f;
    for (int i = begin + lane; i < end; i += 32) {
        const int s = srcs[i];
        const float4 sv = *(const float4*)&ssrc[s * 4];
        float v;
        v = sv.x + sd0; v = v > 0.f ? v : 0.2f * v; d0 += expf(v);
        v = sv.y + sd1; v = v > 0.f ? v : 0.2f * v; d1 += expf(v);
        v = sv.z + sd2; v = v > 0.f ? v : 0.2f * v; d2 += expf(v);
        v = sv.w + sd3; v = v > 0.f ? v : 0.2f * v; d3 += expf(v);
    }
#pragma unroll
    for (int o = 16; o; o >>= 1) {
        d0 += __shfl_xor_sync(0xffffffffu, d0, o);
        d1 += __shfl_xor_sync(0xffffffffu, d1, o);
        d2 += __shfl_xor_sync(0xffffffffu, d2, o);
        d3 += __shfl_xor_sync(0xffffffffu, d3, o);
    }
    const float dh  = (h == 0) ? d0 : (h == 1) ? d1 : (h == 2) ? d2 : d3;
    const float sdh = (h == 0) ? sd0 : (h == 1) ? sd1 : (h == 2) ? sd2 : sd3;
    const float invd = 1.0f / (dh + 1e-8f);

    float acc[PER];
#pragma unroll
    for (int j = 0; j < PER; j++) acc[j] = 0.f;

    const int colbase = lane * PER;
    for (int i = begin; i < end; i++) {
        const int s = srcs[i];
        float e = ssrc[s * 4 + h] + sdh;
        e = e > 0.f ? e : 0.2f * e;
        const float alpha = expf(e) * invd;
        const float4* w = (const float4*)&Wx[(long long)s * DOUT + colbase];
#pragma unroll
        for (int j = 0; j < PER / 4; j++) {
            const float4 wv = w[j];
            acc[j * 4 + 0] = fmaf(alpha, wv.x, acc[j * 4 + 0]);
            acc[j * 4 + 1] = fmaf(alpha, wv.y, acc[j * 4 + 1]);
            acc[j * 4 + 2] = fmaf(alpha, wv.z, acc[j * 4 + 2]);
            acc[j * 4 + 3] = fmaf(alpha, wv.w, acc[j * 4 + 3]);
        }
    }

    float sum = 0.f, sumsq = 0.f;
#pragma unroll
    for (int j = 0; j < PER; j++) {
        float v = acc[j];
        v = (v > 0.f) ? v : expm1f(v);
        acc[j] = v;
        sum += v;
        sumsq = fmaf(v, v, sumsq);
    }
#pragma unroll
    for (int o = 16; o; o >>= 1) {
        sum   += __shfl_xor_sync(0xffffffffu, sum, o);
        sumsq += __shfl_xor_sync(0xffffffffu, sumsq, o);
    }
    const float inv = 1.0f / (float)DOUT;
    const float mu  = sum * inv;
    const float var = sumsq * inv - mu * mu;
    const float rs  = rsqrtf(var + 1e-5f);

    float* orow = &out[(long long)node * DOUT + colbase];
#pragma unroll
    for (int j = 0; j < PER / 4; j++) {
        const float4 gv = *(const float4*)&g[colbase + j * 4];
        const float4 bv = *(const float4*)&b[colbase + j * 4];
        float4 ov;
        ov.x = (acc[j * 4 + 0] - mu) * rs * gv.x + bv.x;
        ov.y = (acc[j * 4 + 1] - mu) * rs * gv.y + bv.y;
        ov.z = (acc[j * 4 + 2] - mu) * rs * gv.z + bv.z;
        ov.w = (acc[j * 4 + 3] - mu) * rs * gv.w + bv.w;
        *(float4*)&orow[j * 4] = ov;
    }
}

// ---------------- host orchestration ------------------------------------------
static void run_layer(const float* x, int din, int dout, int hd,
                      const float* W, const float* a,
                      const float* g, const float* b,
                      const int* rowptr, const int* srcs,
                      float* wx, float* ssrc, float* sdst, float* out)
{
    const int N = NNODES;

    {
        dim3 grid(dout / BN > 0 ? dout / BN : 1, (N + BM - 1) / BM);
        sgemm_kernel<<<grid, 256>>>(x, W, wx, N, dout, din);
    }
    {
        const long long threads = (long long)N * HEADS * 32;
        scores_kernel<<<(int)((threads + 255) / 256), 256>>>(wx, a, ssrc, sdst, N, hd);
    }
    {
        const long long threads = (long long)N * 32;
        const int blocks = (int)((threads + 255) / 256);
        if (dout == 256)
            gat_aggregate_ln_kernel<256><<<blocks, 256>>>(rowptr, srcs, ssrc, sdst, wx, g, b, out, N);
        else
            gat_aggregate_ln_kernel<512><<<blocks, 256>>>(rowptr, srcs, ssrc, sdst, wx, g, b, out, N);
    }
}

extern "C" void kernel_launch(void* const* d_in, const int* in_sizes, int n_in,
                              void* d_out, int out_size)
{
    const float* x0 = (const float*)d_in[0];
    const int*   ei = (const int*)d_in[1];
    const float* W1 = (const float*)d_in[2];
    const float* a1 = (const float*)d_in[3];
    const float* g1 = (const float*)d_in[4];
    const float* b1 = (const float*)d_in[5];
    const float* W2 = (const float*)d_in[6];
    const float* a2 = (const float*)d_in[7];
    const float* g2 = (const float*)d_in[8];
    const float* b2 = (const float*)d_in[9];
    const float* W3 = (const float*)d_in[10];
    const float* a3 = (const float*)d_in[11];
    const float* g3 = (const float*)d_in[12];
    const float* b3 = (const float*)d_in[13];

    const int* src = ei;
    const int* dst = ei + NEDGES;

    float *wx, *bufA, *bufB, *ssrc, *sdst;
    int *cnt, *rowptr, *fill, *srcs;
    cudaGetSymbolAddress((void**)&wx,     g_Wx);
    cudaGetSymbolAddress((void**)&bufA,   g_bufA);
    cudaGetSymbolAddress((void**)&bufB,   g_bufB);
    cudaGetSymbolAddress((void**)&ssrc,   g_ssrc);
    cudaGetSymbolAddress((void**)&sdst,   g_sdst);
    cudaGetSymbolAddress((void**)&cnt,    g_cnt);
    cudaGetSymbolAddress((void**)&rowptr, g_rowptr);
    cudaGetSymbolAddress((void**)&fill,   g_fill);
    cudaGetSymbolAddress((void**)&srcs,   g_srcs);

    cudaMemsetAsync(cnt, 0, NNODES * sizeof(int), 0);
    hist_kernel<<<(NEDGES + 255) / 256, 256>>>(dst, cnt, NEDGES);
    scan_kernel<<<1, 1024>>>(cnt, rowptr, fill, NNODES);
    scatter_kernel<<<(NEDGES + 255) / 256, 256>>>(src, dst, fill, srcs, NEDGES);

    float* outf = (float*)d_out;

    run_layer(x0,   523, 256,  64, W1, a1, g1, b1, rowptr, srcs, wx, ssrc, sdst, bufA);
    run_layer(bufA, 256, 256,  64, W2, a2, g2, b2, rowptr, srcs, wx, ssrc, sdst, bufB);
    run_layer(bufB, 256, 512, 128, W3, a3, g3, b3, rowptr, srcs, wx, ssrc, sdst, outf);
}

// round 7
// speedup vs baseline: 1.2371x; 1.2371x over previous
#include <cuda_runtime.h>
#include <math.h>

#define NNODES 50000
#define NEDGES 400000
#define HEADS  4

typedef unsigned long long ull;

// ---------------- scratch (device globals; no allocation allowed) -------------
__device__ float g_Wx  [NNODES * 512];
__device__ float g_bufA[NNODES * 256];
__device__ float g_bufB[NNODES * 256];
__device__ float g_ssrc[NNODES * HEADS];
__device__ float g_sdst[NNODES * HEADS];
__device__ int g_cnt   [NNODES];
__device__ int g_rowptr[NNODES + 1];
__device__ int g_fill  [NNODES];
__device__ int g_srcs  [NEDGES];

// ------- SGEMM, FFMA2, 128x128 tile, 128 threads, 16x8 micro, 2 CTA/SM --------
#define BM 128
#define BN 128
#define BK 8
#define TM 16
#define TN 8

__device__ __forceinline__ ull pack_dup(float x) {
    ull r;
    asm("mov.b64 %0, {%1, %1};" : "=l"(r) : "f"(x));
    return r;
}
__device__ __forceinline__ void ffma2(ull& d, ull a, ull b) {
    asm("fma.rn.f32x2 %0, %1, %2, %0;" : "+l"(d) : "l"(a), "l"(b));
}

__global__ __launch_bounds__(128, 2)
void sgemm_kernel(const float* __restrict__ A, const float* __restrict__ B,
                  float* __restrict__ C, int M, int N, int K)
{
    // A stored pre-duplicated: As2[k][m] = {A, A} (8 bytes per element)
    __shared__ __align__(16) ull   As2[2][BK][BM];
    __shared__ __align__(16) float Bs [2][BK][BN];

    const int tid = threadIdx.x;
    const int block_row = blockIdx.y * BM;
    const int block_col = blockIdx.x * BN;

    const int tx = tid % 16;           // col group: 8 cols each  -> 128
    const int ty = tid / 16;           // row group: 16 rows each -> 128

    const int a_row = tid;             // 0..127 (one A row per thread)
    const int b_row = tid >> 4;        // 0..7
    const int b_col = (tid & 15) * 8;  // 0..120

    const int gr_a = block_row + a_row;
    const bool a_valid = (gr_a < M);
    const float* arow = a_valid ? &A[(long long)gr_a * K] : A;

    ull acc2[TM][TN / 2];
#pragma unroll
    for (int i = 0; i < TM; i++)
#pragma unroll
        for (int j = 0; j < TN / 2; j++) acc2[i][j] = 0ull;

    // ---- preload tile 0 ----
    {
#pragma unroll
        for (int kk = 0; kk < BK; kk++) {
            float v = 0.0f;
            if (a_valid && kk < K) v = arow[kk];
            As2[0][kk][a_row] = pack_dup(v);
        }
        float4 v0 = make_float4(0.f, 0.f, 0.f, 0.f), v1 = v0;
        if (b_row < K) {
            const float* brow = &B[(long long)b_row * N + block_col];
            v0 = *(const float4*)&brow[b_col];
            v1 = *(const float4*)&brow[b_col + 4];
        }
        *(float4*)&Bs[0][b_row][b_col]     = v0;
        *(float4*)&Bs[0][b_row][b_col + 4] = v1;
    }
    __syncthreads();

    int buf = 0;
    for (int k0 = 0; k0 < K; k0 += BK) {
        const int kn = k0 + BK;
        const bool more = kn < K;

        // register prefetch of next tile (A scalar: K may be odd -> no vec loads)
        float pa[BK];
        float4 pb0 = make_float4(0.f, 0.f, 0.f, 0.f), pb1 = pb0;
        if (more) {
#pragma unroll
            for (int i = 0; i < BK; i++)
                pa[i] = (a_valid && (kn + i < K)) ? arow[kn + i] : 0.0f;
            const int gk = kn + b_row;
            if (gk < K) {
                const float* brow = &B[(long long)gk * N + block_col];
                pb0 = *(const float4*)&brow[b_col];
                pb1 = *(const float4*)&brow[b_col + 4];
            }
        }

        // compute on current buffer
#pragma unroll
        for (int k = 0; k < BK; k++) {
            ull a2[TM];
#pragma unroll
            for (int q = 0; q < TM / 2; q++) {
                const ulonglong2 av = *(const ulonglong2*)&As2[buf][k][ty * TM + q * 2];
                a2[q * 2]     = av.x;
                a2[q * 2 + 1] = av.y;
            }
            ull b2[TN / 2];
            {
                const ulonglong2 bA = *(const ulonglong2*)&Bs[buf][k][tx * TN + 0];
                const ulonglong2 bB = *(const ulonglong2*)&Bs[buf][k][tx * TN + 4];
                b2[0] = bA.x; b2[1] = bA.y; b2[2] = bB.x; b2[3] = bB.y;
            }
#pragma unroll
            for (int i = 0; i < TM; i++)
#pragma unroll
                for (int j = 0; j < TN / 2; j++)
                    ffma2(acc2[i][j], a2[i], b2[j]);
        }

        // stage prefetched tile
        if (more) {
#pragma unroll
            for (int kk = 0; kk < BK; kk++)
                As2[buf ^ 1][kk][a_row] = pack_dup(pa[kk]);
            *(float4*)&Bs[buf ^ 1][b_row][b_col]     = pb0;
            *(float4*)&Bs[buf ^ 1][b_row][b_col + 4] = pb1;
        }
        __syncthreads();
        buf ^= 1;
    }

    // store: rows ty*16.., cols tx*8..tx*8+7
#pragma unroll
    for (int i = 0; i < TM; i++) {
        const int gr = block_row + ty * TM + i;
        if (gr < M) {
            float out[TN];
#pragma unroll
            for (int j = 0; j < TN / 2; j++) {
                const float2 f = *(const float2*)&acc2[i][j];
                out[2 * j]     = f.x;
                out[2 * j + 1] = f.y;
            }
            float* c = &C[(long long)gr * N + block_col + tx * TN];
            *(float4*)&c[0] = make_float4(out[0], out[1], out[2], out[3]);
            *(float4*)&c[4] = make_float4(out[4], out[5], out[6], out[7]);
        }
    }
}

// ---------------- CSR construction (dst-grouped) -------------------------------
__global__ void hist_kernel(const int* __restrict__ dst, int* __restrict__ cnt, int E)
{
    const int e = blockIdx.x * blockDim.x + threadIdx.x;
    if (e < E) atomicAdd(&cnt[dst[e]], 1);
}

__global__ void scan_kernel(const int* __restrict__ cnt, int* __restrict__ rowptr,
                            int* __restrict__ fill, int n)
{
    __shared__ int sh[1024];
    __shared__ int carry;
    if (threadIdx.x == 0) { carry = 0; rowptr[0] = 0; }
    __syncthreads();
    for (int base = 0; base < n; base += 1024) {
        const int i = base + (int)threadIdx.x;
        const int v = (i < n) ? cnt[i] : 0;
        sh[threadIdx.x] = v;
        __syncthreads();
#pragma unroll
        for (int o = 1; o < 1024; o <<= 1) {
            int t = (threadIdx.x >= (unsigned)o) ? sh[threadIdx.x - o] : 0;
            __syncthreads();
            sh[threadIdx.x] += t;
            __syncthreads();
        }
        const int incl = sh[threadIdx.x];
        if (i < n) {
            rowptr[i + 1] = carry + incl;
            fill[i] = carry + incl - v;
        }
        __syncthreads();
        if (threadIdx.x == 0) carry += sh[1023];
        __syncthreads();
    }
}

__global__ void scatter_kernel(const int* __restrict__ src, const int* __restrict__ dst,
                               int* __restrict__ fill, int* __restrict__ srcs, int E)
{
    const int e = blockIdx.x * blockDim.x + threadIdx.x;
    if (e >= E) return;
    const int pos = atomicAdd(&fill[dst[e]], 1);
    srcs[pos] = src[e];
}

// ---------------- per-(node,head) attention scores ----------------------------
__global__ void scores_kernel(const float* __restrict__ Wx,
                              const float* __restrict__ a,
                              float* __restrict__ s_src, float* __restrict__ s_dst,
                              int n, int hd)
{
    const int warp = (blockIdx.x * blockDim.x + threadIdx.x) >> 5;
    const int lane = threadIdx.x & 31;
    if (warp >= n * HEADS) return;
    const int node = warp / HEADS;
    const int h    = warp % HEADS;
    const float* row = Wx + (long long)node * HEADS * hd + h * hd;
    float ss = 0.f, sd = 0.f;
    for (int d = lane; d < hd; d += 32) {
        const float v = row[d];
        ss = fmaf(v, a[d], ss);
        sd = fmaf(v, a[hd + d], sd);
    }
#pragma unroll
    for (int o = 16; o; o >>= 1) {
        ss += __shfl_xor_sync(0xffffffffu, ss, o);
        sd += __shfl_xor_sync(0xffffffffu, sd, o);
    }
    if (lane == 0) {
        s_src[node * HEADS + h] = ss;
        s_dst[node * HEADS + h] = sd;
    }
}

// ------ fused edge-softmax + weighted aggregation + ELU + LayerNorm -----------
template <int DOUT>
__global__ __launch_bounds__(256)
void gat_aggregate_ln_kernel(const int* __restrict__ rowptr,
                             const int* __restrict__ srcs,
                             const float* __restrict__ ssrc,
                             const float* __restrict__ sdst,
                             const float* __restrict__ Wx,
                             const float* __restrict__ g,
                             const float* __restrict__ b,
                             float* __restrict__ out, int n)
{
    const int warp = (blockIdx.x * blockDim.x + threadIdx.x) >> 5;
    const int lane = threadIdx.x & 31;
    if (warp >= n) return;
    const int node = warp;
    const int begin = rowptr[node];
    const int end   = rowptr[node + 1];

    constexpr int PER = DOUT / 32;
    const int h = lane >> 3;

    const float4 sdv = *(const float4*)&sdst[node * 4];
    const float sd0 = sdv.x, sd1 = sdv.y, sd2 = sdv.z, sd3 = sdv.w;

    float d0 = 0.f, d1 = 0.f, d2 = 0.f, d3 = 0.f;
    for (int i = begin + lane; i < end; i += 32) {
        const int s = srcs[i];
        const float4 sv = *(const float4*)&ssrc[s * 4];
        float v;
        v = sv.x + sd0; v = v > 0.f ? v : 0.2f * v; d0 += expf(v);
        v = sv.y + sd1; v = v > 0.f ? v : 0.2f * v; d1 += expf(v);
        v = sv.z + sd2; v = v > 0.f ? v : 0.2f * v; d2 += expf(v);
        v = sv.w + sd3; v = v > 0.f ? v : 0.2f * v; d3 += expf(v);
    }
#pragma unroll
    for (int o = 16; o; o >>= 1) {
        d0 += __shfl_xor_sync(0xffffffffu, d0, o);
        d1 += __shfl_xor_sync(0xffffffffu, d1, o);
        d2 += __shfl_xor_sync(0xffffffffu, d2, o);
        d3 += __shfl_xor_sync(0xffffffffu, d3, o);
    }
    const float dh  = (h == 0) ? d0 : (h == 1) ? d1 : (h == 2) ? d2 : d3;
    const float sdh = (h == 0) ? sd0 : (h == 1) ? sd1 : (h == 2) ? sd2 : sd3;
    const float invd = 1.0f / (dh + 1e-8f);

    float acc[PER];
#pragma unroll
    for (int j = 0; j < PER; j++) acc[j] = 0.f;

    const int colbase = lane * PER;
    for (int i = begin; i < end; i++) {
        const int s = srcs[i];
        float e = ssrc[s * 4 + h] + sdh;
        e = e > 0.f ? e : 0.2f * e;
        const float alpha = expf(e) * invd;
        const float4* w = (const float4*)&Wx[(long long)s * DOUT + colbase];
#pragma unroll
        for (int j = 0; j < PER / 4; j++) {
            const float4 wv = w[j];
            acc[j * 4 + 0] = fmaf(alpha, wv.x, acc[j * 4 + 0]);
            acc[j * 4 + 1] = fmaf(alpha, wv.y, acc[j * 4 + 1]);
            acc[j * 4 + 2] = fmaf(alpha, wv.z, acc[j * 4 + 2]);
            acc[j * 4 + 3] = fmaf(alpha, wv.w, acc[j * 4 + 3]);
        }
    }

    float sum = 0.f, sumsq = 0.f;
#pragma unroll
    for (int j = 0; j < PER; j++) {
        float v = acc[j];
        v = (v > 0.f) ? v : expm1f(v);
        acc[j] = v;
        sum += v;
        sumsq = fmaf(v, v, sumsq);
    }
#pragma unroll
    for (int o = 16; o; o >>= 1) {
        sum   += __shfl_xor_sync(0xffffffffu, sum, o);
        sumsq += __shfl_xor_sync(0xffffffffu, sumsq, o);
    }
    const float inv = 1.0f / (float)DOUT;
    const float mu  = sum * inv;
    const float var = sumsq * inv - mu * mu;
    const float rs  = rsqrtf(var + 1e-5f);

    float* orow = &out[(long long)node * DOUT + colbase];
#pragma unroll
    for (int j = 0; j < PER / 4; j++) {
        const float4 gv = *(const float4*)&g[colbase + j * 4];
        const float4 bv = *(const float4*)&b[colbase + j * 4];
        float4 ov;
        ov.x = (acc[j * 4 + 0] - mu) * rs * gv.x + bv.x;
        ov.y = (acc[j * 4 + 1] - mu) * rs * gv.y + bv.y;
        ov.z = (acc[j * 4 + 2] - mu) * rs * gv.z + bv.z;
        ov.w = (acc[j * 4 + 3] - mu) * rs * gv.w + bv.w;
        *(float4*)&orow[j * 4] = ov;
    }
}

// ---------------- host orchestration ------------------------------------------
static void run_layer(const float* x, int din, int dout, int hd,
                      const float* W, const float* a,
                      const float* g, const float* b,
                      const int* rowptr, const int* srcs,
                      float* wx, float* ssrc, float* sdst, float* out)
{
    const int N = NNODES;

    {
        dim3 grid(dout / BN, (N + BM - 1) / BM);
        sgemm_kernel<<<grid, 128>>>(x, W, wx, N, dout, din);
    }
    {
        const long long threads = (long long)N * HEADS * 32;
        scores_kernel<<<(int)((threads + 255) / 256), 256>>>(wx, a, ssrc, sdst, N, hd);
    }
    {
        const long long threads = (long long)N * 32;
        const int blocks = (int)((threads + 255) / 256);
        if (dout == 256)
            gat_aggregate_ln_kernel<256><<<blocks, 256>>>(rowptr, srcs, ssrc, sdst, wx, g, b, out, N);
        else
            gat_aggregate_ln_kernel<512><<<blocks, 256>>>(rowptr, srcs, ssrc, sdst, wx, g, b, out, N);
    }
}

extern "C" void kernel_launch(void* const* d_in, const int* in_sizes, int n_in,
                              void* d_out, int out_size)
{
    const float* x0 = (const float*)d_in[0];
    const int*   ei = (const int*)d_in[1];
    const float* W1 = (const float*)d_in[2];
    const float* a1 = (const float*)d_in[3];
    const float* g1 = (const float*)d_in[4];
    const float* b1 = (const float*)d_in[5];
    const float* W2 = (const float*)d_in[6];
    const float* a2 = (const float*)d_in[7];
    const float* g2 = (const float*)d_in[8];
    const float* b2 = (const float*)d_in[9];
    const float* W3 = (const float*)d_in[10];
    const float* a3 = (const float*)d_in[11];
    const float* g3 = (const float*)d_in[12];
    const float* b3 = (const float*)d_in[13];

    const int* src = ei;
    const int* dst = ei + NEDGES;

    float *wx, *bufA, *bufB, *ssrc, *sdst;
    int *cnt, *rowptr, *fill, *srcs;
    cudaGetSymbolAddress((void**)&wx,     g_Wx);
    cudaGetSymbolAddress((void**)&bufA,   g_bufA);
    cudaGetSymbolAddress((void**)&bufB,   g_bufB);
    cudaGetSymbolAddress((void**)&ssrc,   g_ssrc);
    cudaGetSymbolAddress((void**)&sdst,   g_sdst);
    cudaGetSymbolAddress((void**)&cnt,    g_cnt);
    cudaGetSymbolAddress((void**)&rowptr, g_rowptr);
    cudaGetSymbolAddress((void**)&fill,   g_fill);
    cudaGetSymbolAddress((void**)&srcs,   g_srcs);

    cudaMemsetAsync(cnt, 0, NNODES * sizeof(int), 0);
    hist_kernel<<<(NEDGES + 255) / 256, 256>>>(dst, cnt, NEDGES);
    scan_kernel<<<1, 1024>>>(cnt, rowptr, fill, NNODES);
    scatter_kernel<<<(NEDGES + 255) / 256, 256>>>(src, dst, fill, srcs, NEDGES);

    float* outf = (float*)d_out;

    run_layer(x0,   523, 256,  64, W1, a1, g1, b1, rowptr, srcs, wx, ssrc, sdst, bufA);
    run_layer(bufA, 256, 256,  64, W2, a2, g2, b2, rowptr, srcs, wx, ssrc, sdst, bufB);
    run_layer(bufB, 256, 512, 128, W3, a3, g3, b3, rowptr, srcs, wx, ssrc, sdst, outf);
}

// round 9
// speedup vs baseline: 1.5785x; 1.2760x over previous
#include <cuda_runtime.h>
#include <cuda_bf16.h>
#include <math.h>
#include <stdint.h>

#define NNODES 50000
#define NEDGES 400000
#define HEADS  4
#define KP1 1600   // padded K' for layer 1 (3*523=1569 -> 1600)
#define KP2 768    // K' for layers 2,3 (3*256)

// ---------------- scratch (device globals; no allocation allowed) -------------
__device__ float g_Wx  [NNODES * 512];                  // GEMM output (fp32)
__device__ __nv_bfloat16 g_Abf[(size_t)NNODES * KP1];   // augmented A' (bf16)
__device__ __nv_bfloat16 g_Bbf[512 * KP1];              // augmented B' (bf16)
__device__ float g_ssrc[NNODES * HEADS];
__device__ float g_sdst[NNODES * HEADS];
__device__ int g_cnt   [NNODES];
__device__ int g_rowptr[NNODES + 1];
__device__ int g_fill  [NNODES];
__device__ int g_srcs  [NEDGES];

// ============================ PTX helpers (sm_80-level only) ===================
__device__ __forceinline__ uint32_t smem_u32(const void* p) {
    uint32_t a;
    asm("{ .reg .u64 t; cvta.to.shared.u64 t, %1; cvt.u32.u64 %0, t; }" : "=r"(a) : "l"(p));
    return a;
}
__device__ __forceinline__ void ldsm_x4(uint32_t& r0, uint32_t& r1,
                                        uint32_t& r2, uint32_t& r3, uint32_t addr) {
    asm volatile("ldmatrix.sync.aligned.m8n8.x4.shared.b16 {%0,%1,%2,%3}, [%4];"
                 : "=r"(r0), "=r"(r1), "=r"(r2), "=r"(r3) : "r"(addr));
}
__device__ __forceinline__ void mma_bf16(float* c, const uint32_t* a, const uint32_t* b) {
    asm volatile("mma.sync.aligned.m16n8k16.row.col.f32.bf16.bf16.f32 "
                 "{%0,%1,%2,%3}, {%4,%5,%6,%7}, {%8,%9}, {%0,%1,%2,%3};"
                 : "+f"(c[0]), "+f"(c[1]), "+f"(c[2]), "+f"(c[3])
                 : "r"(a[0]), "r"(a[1]), "r"(a[2]), "r"(a[3]), "r"(b[0]), "r"(b[1]));
}
__device__ __forceinline__ void cp_async16(uint32_t smem_addr, const void* g, bool pred) {
    const int sz = pred ? 16 : 0;
    asm volatile("cp.async.cg.shared.global [%0], [%1], 16, %2;"
                 :: "r"(smem_addr), "l"(g), "r"(sz));
}
#define CP_ASYNC_COMMIT() asm volatile("cp.async.commit_group;" ::: "memory")
#define CP_ASYNC_WAIT0()  asm volatile("cp.async.wait_group 0;"  ::: "memory")

// =============== HMMA GEMM: C[M,N] = A'[M,Kp] @ B'[N,Kp]^T ====================
// 128x128 CTA tile, 256 thr (8 warps as 4x2 -> warp tile 32x64), BK=64.
// smem rows padded to 144 B (stride 9*16B -> ldmatrix conflict-free).
#define ROWB 144                            // bytes per smem row
#define MATB (128 * ROWB)                   // 18432 B per matrix tile
#define BUFB (2 * MATB)                     // A + B per buffer
#define GEMM_SMEM (2 * BUFB)                // double buffered = 73728 B

__global__ __launch_bounds__(256, 2)
void hmma_gemm_kernel(const __nv_bfloat16* __restrict__ Aq,
                      const __nv_bfloat16* __restrict__ Bq,
                      float* __restrict__ C, int M, int N, int Kp)
{
    extern __shared__ __align__(16) char smem[];
    const uint32_t smem_base = smem_u32(smem);

    const int tid  = threadIdx.x;
    const int wid  = tid >> 5;
    const int lane = tid & 31;

    const int m0 = blockIdx.y * 128;
    const int n0 = blockIdx.x * 128;

    const int wm = (wid & 3) * 32;    // warp M offset
    const int wn = (wid >> 2) * 64;   // warp N offset

    // G2S loader mapping: thread owns half a row (4 x 16B chunks)
    const int lrow  = tid >> 1;       // 0..127
    const int lhalf = tid & 1;        // 0/1
    const bool a_ok = (m0 + lrow) < M;
    const __nv_bfloat16* Ag = Aq + (size_t)(a_ok ? (m0 + lrow) : 0) * Kp;
    const __nv_bfloat16* Bg = Bq + (size_t)(n0 + lrow) * Kp;   // n0+lrow < N always

    // fragment addressing (per-lane constants)
    const int sub = lane >> 3;        // 0..3 (8x8 submatrix id)
    const int srw = lane & 7;         // row within submatrix
    const uint32_t a_off = (uint32_t)(wm + (sub & 1) * 8 + srw) * ROWB + (sub >> 1) * 16;
    const uint32_t b_off = (uint32_t)(wn + (sub & 1) * 8 + srw) * ROWB + (sub >> 1) * 16;

    float acc[2][8][4];
#pragma unroll
    for (int i = 0; i < 2; i++)
#pragma unroll
        for (int j = 0; j < 8; j++)
#pragma unroll
            for (int r = 0; r < 4; r++) acc[i][j][r] = 0.f;

    const int ntiles = Kp / 64;

    // issue loads of tile t into buffer buf
    auto issue = [&](int t, int buf) {
        const uint32_t sa = smem_base + buf * BUFB;
        const uint32_t sb = sa + MATB;
        const size_t gofs = (size_t)t * 64;   // element offset in K'
#pragma unroll
        for (int q = 0; q < 4; q++) {
            const int c16 = lhalf * 4 + q;                       // 0..7
            const uint32_t sofs = (uint32_t)lrow * ROWB + c16 * 16;
            cp_async16(sa + sofs, (const char*)(Ag + gofs) + c16 * 16, a_ok);
            cp_async16(sb + sofs, (const char*)(Bg + gofs) + c16 * 16, true);
        }
        CP_ASYNC_COMMIT();
    };

    issue(0, 0);
    CP_ASYNC_WAIT0();
    __syncthreads();

    int buf = 0;
    for (int t = 0; t < ntiles; t++) {
        const bool more = (t + 1) < ntiles;
        if (more) issue(t + 1, buf ^ 1);

        const uint32_t sa = smem_base + buf * BUFB;
        const uint32_t sb = sa + MATB;
#pragma unroll
        for (int k0 = 0; k0 < 64; k0 += 16) {
            uint32_t af[2][4];
#pragma unroll
            for (int mi = 0; mi < 2; mi++)
                ldsm_x4(af[mi][0], af[mi][1], af[mi][2], af[mi][3],
                        sa + a_off + mi * 16 * ROWB + k0 * 2);
            uint32_t bf[8][2];
#pragma unroll
            for (int np = 0; np < 4; np++) {
                uint32_t r0, r1, r2, r3;
                ldsm_x4(r0, r1, r2, r3, sb + b_off + np * 16 * ROWB + k0 * 2);
                bf[2 * np][0] = r0; bf[2 * np + 1][0] = r1;
                bf[2 * np][1] = r2; bf[2 * np + 1][1] = r3;
            }
#pragma unroll
            for (int mi = 0; mi < 2; mi++)
#pragma unroll
                for (int ni = 0; ni < 8; ni++)
                    mma_bf16(acc[mi][ni], af[mi], bf[ni]);
        }

        if (more) CP_ASYNC_WAIT0();
        __syncthreads();
        buf ^= 1;
    }

    // epilogue: thread (gid, tig) owns cols n += 2*tig, rows m = gid / gid+8
    const int gid = lane >> 2;
    const int tig = lane & 3;
#pragma unroll
    for (int mi = 0; mi < 2; mi++) {
        const int m1 = m0 + wm + mi * 16 + gid;
        const int m2 = m1 + 8;
#pragma unroll
        for (int ni = 0; ni < 8; ni++) {
            const int nn = n0 + wn + ni * 8 + tig * 2;
            if (m1 < M) *(float2*)&C[(size_t)m1 * N + nn] =
                make_float2(acc[mi][ni][0], acc[mi][ni][1]);
            if (m2 < M) *(float2*)&C[(size_t)m2 * N + nn] =
                make_float2(acc[mi][ni][2], acc[mi][ni][3]);
        }
    }
}

// ====================== fp32 -> split bf16 conversions =========================
__device__ __forceinline__ void split_bf16(float x, __nv_bfloat16& hi, __nv_bfloat16& lo) {
    hi = __float2bfloat16(x);
    lo = __float2bfloat16(x - __bfloat162float(hi));
}

// A' for layer 1 from node_feats: sections [hi | lo | hi], K=523, Kp=1600
__global__ void convertA0_kernel(const float* __restrict__ x,
                                 __nv_bfloat16* __restrict__ out)
{
    const long long idx = (long long)blockIdx.x * blockDim.x + threadIdx.x;
    const long long total = (long long)NNODES * KP1;
    if (idx >= total) return;
    const int m = (int)(idx / KP1);
    const int j = (int)(idx % KP1);
    __nv_bfloat16 v = __float2bfloat16(0.0f);
    if (j < 3 * 523) {
        const int sec = (j < 523) ? 0 : (j < 1046) ? 1 : 2;
        const int k   = j - sec * 523;
        const float xv = x[(long long)m * 523 + k];
        __nv_bfloat16 hi, lo;
        split_bf16(xv, hi, lo);
        v = (sec == 1) ? lo : hi;
    }
    out[idx] = v;
}

// B' from W[K,N]: B'[n, j] sections [hi | hi | lo] of W[k, n]
__global__ void convertW_kernel(const float* __restrict__ W,
                                __nv_bfloat16* __restrict__ out,
                                int K, int Kp, int N)
{
    const long long idx = (long long)blockIdx.x * blockDim.x + threadIdx.x;
    const long long total = (long long)N * Kp;
    if (idx >= total) return;
    const int n = (int)(idx / Kp);
    const int j = (int)(idx % Kp);
    __nv_bfloat16 v = __float2bfloat16(0.0f);
    if (j < 3 * K) {
        const int sec = (j < K) ? 0 : (j < 2 * K) ? 1 : 2;
        const int k   = j - sec * K;
        const float wv = W[(long long)k * N + n];
        __nv_bfloat16 hi, lo;
        split_bf16(wv, hi, lo);
        v = (sec == 2) ? lo : hi;
    }
    out[idx] = v;
}

// ---------------- CSR construction (dst-grouped) -------------------------------
__global__ void hist_kernel(const int* __restrict__ dst, int* __restrict__ cnt, int E)
{
    const int e = blockIdx.x * blockDim.x + threadIdx.x;
    if (e < E) atomicAdd(&cnt[dst[e]], 1);
}

__global__ void scan_kernel(const int* __restrict__ cnt, int* __restrict__ rowptr,
                            int* __restrict__ fill, int n)
{
    __shared__ int sh[1024];
    __shared__ int carry;
    if (threadIdx.x == 0) { carry = 0; rowptr[0] = 0; }
    __syncthreads();
    for (int base = 0; base < n; base += 1024) {
        const int i = base + (int)threadIdx.x;
        const int v = (i < n) ? cnt[i] : 0;
        sh[threadIdx.x] = v;
        __syncthreads();
#pragma unroll
        for (int o = 1; o < 1024; o <<= 1) {
            int t = (threadIdx.x >= (unsigned)o) ? sh[threadIdx.x - o] : 0;
            __syncthreads();
            sh[threadIdx.x] += t;
            __syncthreads();
        }
        const int incl = sh[threadIdx.x];
        if (i < n) {
            rowptr[i + 1] = carry + incl;
            fill[i] = carry + incl - v;
        }
        __syncthreads();
        if (threadIdx.x == 0) carry += sh[1023];
        __syncthreads();
    }
}

__global__ void scatter_kernel(const int* __restrict__ src, const int* __restrict__ dst,
                               int* __restrict__ fill, int* __restrict__ srcs, int E)
{
    const int e = blockIdx.x * blockDim.x + threadIdx.x;
    if (e >= E) return;
    const int pos = atomicAdd(&fill[dst[e]], 1);
    srcs[pos] = src[e];
}

// ---------------- per-(node,head) attention scores ----------------------------
__global__ void scores_kernel(const float* __restrict__ Wx,
                              const float* __restrict__ a,
                              float* __restrict__ s_src, float* __restrict__ s_dst,
                              int n, int hd)
{
    const int warp = (blockIdx.x * blockDim.x + threadIdx.x) >> 5;
    const int lane = threadIdx.x & 31;
    if (warp >= n * HEADS) return;
    const int node = warp / HEADS;
    const int h    = warp % HEADS;
    const float* row = Wx + (long long)node * HEADS * hd + h * hd;
    float ss = 0.f, sd = 0.f;
    for (int d = lane; d < hd; d += 32) {
        const float v = row[d];
        ss = fmaf(v, a[d], ss);
        sd = fmaf(v, a[hd + d], sd);
    }
#pragma unroll
    for (int o = 16; o; o >>= 1) {
        ss += __shfl_xor_sync(0xffffffffu, ss, o);
        sd += __shfl_xor_sync(0xffffffffu, sd, o);
    }
    if (lane == 0) {
        s_src[node * HEADS + h] = ss;
        s_dst[node * HEADS + h] = sd;
    }
}

// ------ fused edge-softmax + aggregation + ELU + LayerNorm --------------------
template <int DOUT, bool OUT_BF16>
__global__ __launch_bounds__(256)
void gat_aggregate_ln_kernel(const int* __restrict__ rowptr,
                             const int* __restrict__ srcs,
                             const float* __restrict__ ssrc,
                             const float* __restrict__ sdst,
                             const float* __restrict__ Wx,
                             const float* __restrict__ g,
                             const float* __restrict__ b,
                             float* __restrict__ outf,
                             __nv_bfloat16* __restrict__ outb, int n)
{
    const int warp = (blockIdx.x * blockDim.x + threadIdx.x) >> 5;
    const int lane = threadIdx.x & 31;
    if (warp >= n) return;
    const int node = warp;
    const int begin = rowptr[node];
    const int end   = rowptr[node + 1];

    constexpr int PER = DOUT / 32;
    const int h = lane >> 3;

    const float4 sdv = *(const float4*)&sdst[node * 4];
    const float sd0 = sdv.x, sd1 = sdv.y, sd2 = sdv.z, sd3 = sdv.w;

    float d0 = 0.f, d1 = 0.f, d2 = 0.f, d3 = 0.f;
    for (int i = begin + lane; i < end; i += 32) {
        const int s = srcs[i];
        const float4 sv = *(const float4*)&ssrc[s * 4];
        float v;
        v = sv.x + sd0; v = v > 0.f ? v : 0.2f * v; d0 += expf(v);
        v = sv.y + sd1; v = v > 0.f ? v : 0.2f * v; d1 += expf(v);
        v = sv.z + sd2; v = v > 0.f ? v : 0.2f * v; d2 += expf(v);
        v = sv.w + sd3; v = v > 0.f ? v : 0.2f * v; d3 += expf(v);
    }
#pragma unroll
    for (int o = 16; o; o >>= 1) {
        d0 += __shfl_xor_sync(0xffffffffu, d0, o);
        d1 += __shfl_xor_sync(0xffffffffu, d1, o);
        d2 += __shfl_xor_sync(0xffffffffu, d2, o);
        d3 += __shfl_xor_sync(0xffffffffu, d3, o);
    }
    const float dh  = (h == 0) ? d0 : (h == 1) ? d1 : (h == 2) ? d2 : d3;
    const float sdh = (h == 0) ? sd0 : (h == 1) ? sd1 : (h == 2) ? sd2 : sd3;
    const float invd = 1.0f / (dh + 1e-8f);

    float acc[PER];
#pragma unroll
    for (int j = 0; j < PER; j++) acc[j] = 0.f;

    const int colbase = lane * PER;
    for (int i = begin; i < end; i++) {
        const int s = srcs[i];
        float e = ssrc[s * 4 + h] + sdh;
        e = e > 0.f ? e : 0.2f * e;
        const float alpha = expf(e) * invd;
        const float4* w = (const float4*)&Wx[(long long)s * DOUT + colbase];
#pragma unroll
        for (int j = 0; j < PER / 4; j++) {
            const float4 wv = w[j];
            acc[j * 4 + 0] = fmaf(alpha, wv.x, acc[j * 4 + 0]);
            acc[j * 4 + 1] = fmaf(alpha, wv.y, acc[j * 4 + 1]);
            acc[j * 4 + 2] = fmaf(alpha, wv.z, acc[j * 4 + 2]);
            acc[j * 4 + 3] = fmaf(alpha, wv.w, acc[j * 4 + 3]);
        }
    }

    float sum = 0.f, sumsq = 0.f;
#pragma unroll
    for (int j = 0; j < PER; j++) {
        float v = acc[j];
        v = (v > 0.f) ? v : expm1f(v);
        acc[j] = v;
        sum += v;
        sumsq = fmaf(v, v, sumsq);
    }
#pragma unroll
    for (int o = 16; o; o >>= 1) {
        sum   += __shfl_xor_sync(0xffffffffu, sum, o);
        sumsq += __shfl_xor_sync(0xffffffffu, sumsq, o);
    }
    const float inv = 1.0f / (float)DOUT;
    const float mu  = sum * inv;
    const float var = sumsq * inv - mu * mu;
    const float rs  = rsqrtf(var + 1e-5f);

    if (OUT_BF16) {
        union { __nv_bfloat16 b16[8]; uint4 v; } uhi, ulo;
#pragma unroll
        for (int j = 0; j < PER; j++) {
            const float fv = (acc[j] - mu) * rs * g[colbase + j] + b[colbase + j];
            split_bf16(fv, uhi.b16[j], ulo.b16[j]);
        }
        __nv_bfloat16* arow = outb + (size_t)node * (3 * DOUT);
        *(uint4*)&arow[colbase]            = uhi.v;   // sec 0: hi
        *(uint4*)&arow[DOUT + colbase]     = ulo.v;   // sec 1: lo
        *(uint4*)&arow[2 * DOUT + colbase] = uhi.v;   // sec 2: hi
    } else {
        float* orow = &outf[(long long)node * DOUT + colbase];
#pragma unroll
        for (int j = 0; j < PER / 4; j++) {
            const float4 gv = *(const float4*)&g[colbase + j * 4];
            const float4 bv = *(const float4*)&b[colbase + j * 4];
            float4 ov;
            ov.x = (acc[j * 4 + 0] - mu) * rs * gv.x + bv.x;
            ov.y = (acc[j * 4 + 1] - mu) * rs * gv.y + bv.y;
            ov.z = (acc[j * 4 + 2] - mu) * rs * gv.z + bv.z;
            ov.w = (acc[j * 4 + 3] - mu) * rs * gv.w + bv.w;
            *(float4*)&orow[j * 4] = ov;
        }
    }
}

// ---------------- host orchestration ------------------------------------------
extern "C" void kernel_launch(void* const* d_in, const int* in_sizes, int n_in,
                              void* d_out, int out_size)
{
    const float* x0 = (const float*)d_in[0];
    const int*   ei = (const int*)d_in[1];
    const float* W1 = (const float*)d_in[2];
    const float* a1 = (const float*)d_in[3];
    const float* g1 = (const float*)d_in[4];
    const float* b1 = (const float*)d_in[5];
    const float* W2 = (const float*)d_in[6];
    const float* a2 = (const float*)d_in[7];
    const float* g2 = (const float*)d_in[8];
    const float* b2 = (const float*)d_in[9];
    const float* W3 = (const float*)d_in[10];
    const float* a3 = (const float*)d_in[11];
    const float* g3 = (const float*)d_in[12];
    const float* b3 = (const float*)d_in[13];

    const int* src = ei;
    const int* dst = ei + NEDGES;

    float *wx, *ssrc, *sdst;
    __nv_bfloat16 *abf, *bbf;
    int *cnt, *rowptr, *fill, *srcs;
    cudaGetSymbolAddress((void**)&wx,     g_Wx);
    cudaGetSymbolAddress((void**)&abf,    g_Abf);
    cudaGetSymbolAddress((void**)&bbf,    g_Bbf);
    cudaGetSymbolAddress((void**)&ssrc,   g_ssrc);
    cudaGetSymbolAddress((void**)&sdst,   g_sdst);
    cudaGetSymbolAddress((void**)&cnt,    g_cnt);
    cudaGetSymbolAddress((void**)&rowptr, g_rowptr);
    cudaGetSymbolAddress((void**)&fill,   g_fill);
    cudaGetSymbolAddress((void**)&srcs,   g_srcs);

    cudaFuncSetAttribute(hmma_gemm_kernel,
                         cudaFuncAttributeMaxDynamicSharedMemorySize, GEMM_SMEM);

    float* outf = (float*)d_out;
    const int N = NNODES;
    const int mtiles = (N + 127) / 128;

    // ---- CSR build (edge_index identical for all 3 layers) ----
    cudaMemsetAsync(cnt, 0, NNODES * sizeof(int), 0);
    hist_kernel<<<(NEDGES + 255) / 256, 256>>>(dst, cnt, NEDGES);
    scan_kernel<<<1, 1024>>>(cnt, rowptr, fill, NNODES);
    scatter_kernel<<<(NEDGES + 255) / 256, 256>>>(src, dst, fill, srcs, NEDGES);

    // ---- layer 1: 523 -> 256 ----
    {
        const long long ta = (long long)NNODES * KP1;
        convertA0_kernel<<<(int)((ta + 255) / 256), 256>>>(x0, abf);
        const long long tb = (long long)256 * KP1;
        convertW_kernel<<<(int)((tb + 255) / 256), 256>>>(W1, bbf, 523, KP1, 256);
        dim3 grid(256 / 128, mtiles);
        hmma_gemm_kernel<<<grid, 256, GEMM_SMEM>>>(abf, bbf, wx, N, 256, KP1);
        scores_kernel<<<(N * HEADS * 32 + 255) / 256, 256>>>(wx, a1, ssrc, sdst, N, 64);
        gat_aggregate_ln_kernel<256, true><<<(N * 32 + 255) / 256, 256>>>(
            rowptr, srcs, ssrc, sdst, wx, g1, b1, nullptr, abf, N);
    }
    // ---- layer 2: 256 -> 256 ----
    {
        const long long tb = (long long)256 * KP2;
        convertW_kernel<<<(int)((tb + 255) / 256), 256>>>(W2, bbf, 256, KP2, 256);
        dim3 grid(256 / 128, mtiles);
        hmma_gemm_kernel<<<grid, 256, GEMM_SMEM>>>(abf, bbf, wx, N, 256, KP2);
        scores_kernel<<<(N * HEADS * 32 + 255) / 256, 256>>>(wx, a2, ssrc, sdst, N, 64);
        gat_aggregate_ln_kernel<256, true><<<(N * 32 + 255) / 256, 256>>>(
            rowptr, srcs, ssrc, sdst, wx, g2, b2, nullptr, abf, N);
    }
    // ---- layer 3: 256 -> 512, fp32 out ----
    {
        const long long tb = (long long)512 * KP2;
        convertW_kernel<<<(int)((tb + 255) / 256), 256>>>(W3, bbf, 256, KP2, 512);
        dim3 grid(512 / 128, mtiles);
        hmma_gemm_kernel<<<grid, 256, GEMM_SMEM>>>(abf, bbf, wx, N, 512, KP2);
        scores_kernel<<<(N * HEADS * 32 + 255) / 256, 256>>>(wx, a3, ssrc, sdst, N, 128);
        gat_aggregate_ln_kernel<512, false><<<(N * 32 + 255) / 256, 256>>>(
            rowptr, srcs, ssrc, sdst, wx, g3, b3, outf, nullptr, N);
    }
}

// round 10
// speedup vs baseline: 1.8302x; 1.1595x over previous
#include <cuda_runtime.h>
#include <cuda_bf16.h>
#include <math.h>
#include <stdint.h>

#define NNODES 50000
#define NEDGES 400000
#define HEADS  4
#define KP1 1600   // padded K' for layer 1 (3*523=1569 -> 1600)
#define KP2 768    // K' for layers 2,3 (3*256)

// ---------------- scratch (device globals; no allocation allowed) -------------
__device__ float g_Wx  [NNODES * 512];                  // GEMM output (fp32)
__device__ __nv_bfloat16 g_Abf[(size_t)NNODES * KP1];   // augmented A' (bf16)
__device__ __nv_bfloat16 g_Bbf[512 * KP1];              // augmented B' (bf16)
__device__ float g_ssrc[NNODES * HEADS];
__device__ float g_sdst[NNODES * HEADS];
__device__ int g_cnt   [NNODES];
__device__ int g_rowptr[NNODES + 1];
__device__ int g_fill  [NNODES];
__device__ int g_srcs  [NEDGES];

// ============================ PTX helpers (sm_80-level only) ===================
__device__ __forceinline__ uint32_t smem_u32(const void* p) {
    uint32_t a;
    asm("{ .reg .u64 t; cvta.to.shared.u64 t, %1; cvt.u32.u64 %0, t; }" : "=r"(a) : "l"(p));
    return a;
}
__device__ __forceinline__ void ldsm_x4(uint32_t& r0, uint32_t& r1,
                                        uint32_t& r2, uint32_t& r3, uint32_t addr) {
    asm volatile("ldmatrix.sync.aligned.m8n8.x4.shared.b16 {%0,%1,%2,%3}, [%4];"
                 : "=r"(r0), "=r"(r1), "=r"(r2), "=r"(r3) : "r"(addr));
}
__device__ __forceinline__ void mma_bf16(float* c, const uint32_t* a, const uint32_t* b) {
    asm volatile("mma.sync.aligned.m16n8k16.row.col.f32.bf16.bf16.f32 "
                 "{%0,%1,%2,%3}, {%4,%5,%6,%7}, {%8,%9}, {%0,%1,%2,%3};"
                 : "+f"(c[0]), "+f"(c[1]), "+f"(c[2]), "+f"(c[3])
                 : "r"(a[0]), "r"(a[1]), "r"(a[2]), "r"(a[3]), "r"(b[0]), "r"(b[1]));
}
__device__ __forceinline__ void cp_async16(uint32_t smem_addr, const void* g, bool pred) {
    const int sz = pred ? 16 : 0;
    asm volatile("cp.async.cg.shared.global [%0], [%1], 16, %2;"
                 :: "r"(smem_addr), "l"(g), "r"(sz));
}
#define CP_ASYNC_COMMIT() asm volatile("cp.async.commit_group;" ::: "memory")
#define CP_ASYNC_WAIT0()  asm volatile("cp.async.wait_group 0;"  ::: "memory")

// =============== HMMA GEMM: C[M,N] = A'[M,Kp] @ B'[N,Kp]^T ====================
// 128x128 CTA tile, 256 thr (8 warps as 4x2 -> warp tile 32x64), BK=64.
// smem rows padded to 144 B (stride 9*16B -> ldmatrix conflict-free).
#define ROWB 144                            // bytes per smem row
#define MATB (128 * ROWB)                   // 18432 B per matrix tile
#define BUFB (2 * MATB)                     // A + B per buffer
#define GEMM_SMEM (2 * BUFB)                // double buffered = 73728 B

__global__ __launch_bounds__(256, 2)
void hmma_gemm_kernel(const __nv_bfloat16* __restrict__ Aq,
                      const __nv_bfloat16* __restrict__ Bq,
                      float* __restrict__ C, int M, int N, int Kp)
{
    extern __shared__ __align__(16) char smem[];
    const uint32_t smem_base = smem_u32(smem);

    const int tid  = threadIdx.x;
    const int wid  = tid >> 5;
    const int lane = tid & 31;

    const int m0 = blockIdx.y * 128;
    const int n0 = blockIdx.x * 128;

    const int wm = (wid & 3) * 32;    // warp M offset
    const int wn = (wid >> 2) * 64;   // warp N offset

    // G2S loader mapping: thread owns half a row (4 x 16B chunks)
    const int lrow  = tid >> 1;       // 0..127
    const int lhalf = tid & 1;        // 0/1
    const bool a_ok = (m0 + lrow) < M;
    const __nv_bfloat16* Ag = Aq + (size_t)(a_ok ? (m0 + lrow) : 0) * Kp;
    const __nv_bfloat16* Bg = Bq + (size_t)(n0 + lrow) * Kp;

    const int sub = lane >> 3;        // 0..3 (8x8 submatrix id)
    const int srw = lane & 7;         // row within submatrix
    const uint32_t a_off = (uint32_t)(wm + (sub & 1) * 8 + srw) * ROWB + (sub >> 1) * 16;
    const uint32_t b_off = (uint32_t)(wn + (sub & 1) * 8 + srw) * ROWB + (sub >> 1) * 16;

    float acc[2][8][4];
#pragma unroll
    for (int i = 0; i < 2; i++)
#pragma unroll
        for (int j = 0; j < 8; j++)
#pragma unroll
            for (int r = 0; r < 4; r++) acc[i][j][r] = 0.f;

    const int ntiles = Kp / 64;

    auto issue = [&](int t, int buf) {
        const uint32_t sa = smem_base + buf * BUFB;
        const uint32_t sb = sa + MATB;
        const size_t gofs = (size_t)t * 64;
#pragma unroll
        for (int q = 0; q < 4; q++) {
            const int c16 = lhalf * 4 + q;
            const uint32_t sofs = (uint32_t)lrow * ROWB + c16 * 16;
            cp_async16(sa + sofs, (const char*)(Ag + gofs) + c16 * 16, a_ok);
            cp_async16(sb + sofs, (const char*)(Bg + gofs) + c16 * 16, true);
        }
        CP_ASYNC_COMMIT();
    };

    issue(0, 0);
    CP_ASYNC_WAIT0();
    __syncthreads();

    int buf = 0;
    for (int t = 0; t < ntiles; t++) {
        const bool more = (t + 1) < ntiles;
        if (more) issue(t + 1, buf ^ 1);

        const uint32_t sa = smem_base + buf * BUFB;
        const uint32_t sb = sa + MATB;
#pragma unroll
        for (int k0 = 0; k0 < 64; k0 += 16) {
            uint32_t af[2][4];
#pragma unroll
            for (int mi = 0; mi < 2; mi++)
                ldsm_x4(af[mi][0], af[mi][1], af[mi][2], af[mi][3],
                        sa + a_off + mi * 16 * ROWB + k0 * 2);
            uint32_t bf[8][2];
#pragma unroll
            for (int np = 0; np < 4; np++) {
                uint32_t r0, r1, r2, r3;
                ldsm_x4(r0, r1, r2, r3, sb + b_off + np * 16 * ROWB + k0 * 2);
                bf[2 * np][0] = r0; bf[2 * np + 1][0] = r1;
                bf[2 * np][1] = r2; bf[2 * np + 1][1] = r3;
            }
#pragma unroll
            for (int mi = 0; mi < 2; mi++)
#pragma unroll
                for (int ni = 0; ni < 8; ni++)
                    mma_bf16(acc[mi][ni], af[mi], bf[ni]);
        }

        if (more) CP_ASYNC_WAIT0();
        __syncthreads();
        buf ^= 1;
    }

    const int gid = lane >> 2;
    const int tig = lane & 3;
#pragma unroll
    for (int mi = 0; mi < 2; mi++) {
        const int m1 = m0 + wm + mi * 16 + gid;
        const int m2 = m1 + 8;
#pragma unroll
        for (int ni = 0; ni < 8; ni++) {
            const int nn = n0 + wn + ni * 8 + tig * 2;
            if (m1 < M) *(float2*)&C[(size_t)m1 * N + nn] =
                make_float2(acc[mi][ni][0], acc[mi][ni][1]);
            if (m2 < M) *(float2*)&C[(size_t)m2 * N + nn] =
                make_float2(acc[mi][ni][2], acc[mi][ni][3]);
        }
    }
}

// ====================== fp32 -> split bf16 conversions =========================
__device__ __forceinline__ void split_bf16(float x, __nv_bfloat16& hi, __nv_bfloat16& lo) {
    hi = __float2bfloat16(x);
    lo = __float2bfloat16(x - __bfloat162float(hi));
}

// A' for layer 1: one block per node row; sections [hi | lo | hi], K=523, Kp=1600
__global__ __launch_bounds__(256)
void convertA0_kernel(const float* __restrict__ x, __nv_bfloat16* __restrict__ out)
{
    const int m = blockIdx.x;
    const float* xr = x + (size_t)m * 523;
    __nv_bfloat16* orow = out + (size_t)m * KP1;
#pragma unroll
    for (int q = 0; q < 3; q++) {
        const int k = q * 256 + (int)threadIdx.x;
        if (k < 523) {
            __nv_bfloat16 hi, lo;
            split_bf16(xr[k], hi, lo);
            orow[k]        = hi;
            orow[523 + k]  = lo;
            orow[1046 + k] = hi;
        }
    }
    // zero pad [1569, 1600)
    const int j = 1569 + (int)threadIdx.x;
    if (j < KP1) orow[j] = __float2bfloat16(0.0f);
}

// B' from W[K,N]: one block per output row n; sections [hi | hi | lo]
__global__ __launch_bounds__(256)
void convertW_kernel(const float* __restrict__ W, __nv_bfloat16* __restrict__ out,
                     int K, int Kp, int N)
{
    const int n = blockIdx.x;
    __nv_bfloat16* orow = out + (size_t)n * Kp;
    for (int k = threadIdx.x; k < K; k += 256) {
        __nv_bfloat16 hi, lo;
        split_bf16(W[(size_t)k * N + n], hi, lo);
        orow[k]         = hi;
        orow[K + k]     = hi;
        orow[2 * K + k] = lo;
    }
    for (int j = 3 * K + threadIdx.x; j < Kp; j += 256)
        orow[j] = __float2bfloat16(0.0f);
}

// ---------------- CSR construction (dst-grouped) -------------------------------
__global__ void hist_kernel(const int* __restrict__ dst, int* __restrict__ cnt, int E)
{
    const int e = blockIdx.x * blockDim.x + threadIdx.x;
    if (e < E) atomicAdd(&cnt[dst[e]], 1);
}

__global__ void scan_kernel(const int* __restrict__ cnt, int* __restrict__ rowptr,
                            int* __restrict__ fill, int n)
{
    __shared__ int sh[1024];
    __shared__ int carry;
    if (threadIdx.x == 0) { carry = 0; rowptr[0] = 0; }
    __syncthreads();
    for (int base = 0; base < n; base += 1024) {
        const int i = base + (int)threadIdx.x;
        const int v = (i < n) ? cnt[i] : 0;
        sh[threadIdx.x] = v;
        __syncthreads();
#pragma unroll
        for (int o = 1; o < 1024; o <<= 1) {
            int t = (threadIdx.x >= (unsigned)o) ? sh[threadIdx.x - o] : 0;
            __syncthreads();
            sh[threadIdx.x] += t;
            __syncthreads();
        }
        const int incl = sh[threadIdx.x];
        if (i < n) {
            rowptr[i + 1] = carry + incl;
            fill[i] = carry + incl - v;
        }
        __syncthreads();
        if (threadIdx.x == 0) carry += sh[1023];
        __syncthreads();
    }
}

__global__ void scatter_kernel(const int* __restrict__ src, const int* __restrict__ dst,
                               int* __restrict__ fill, int* __restrict__ srcs, int E)
{
    const int e = blockIdx.x * blockDim.x + threadIdx.x;
    if (e >= E) return;
    const int pos = atomicAdd(&fill[dst[e]], 1);
    srcs[pos] = src[e];
}

// ---------------- per-(node,head) attention scores ----------------------------
__global__ void scores_kernel(const float* __restrict__ Wx,
                              const float* __restrict__ a,
                              float* __restrict__ s_src, float* __restrict__ s_dst,
                              int n, int hd)
{
    const int warp = (blockIdx.x * blockDim.x + threadIdx.x) >> 5;
    const int lane = threadIdx.x & 31;
    if (warp >= n * HEADS) return;
    const int node = warp / HEADS;
    const int h    = warp % HEADS;
    const float* row = Wx + (long long)node * HEADS * hd + h * hd;
    float ss = 0.f, sd = 0.f;
    for (int d = lane; d < hd; d += 32) {
        const float v = row[d];
        ss = fmaf(v, a[d], ss);
        sd = fmaf(v, a[hd + d], sd);
    }
#pragma unroll
    for (int o = 16; o; o >>= 1) {
        ss += __shfl_xor_sync(0xffffffffu, ss, o);
        sd += __shfl_xor_sync(0xffffffffu, sd, o);
    }
    if (lane == 0) {
        s_src[node * HEADS + h] = ss;
        s_dst[node * HEADS + h] = sd;
    }
}

// ------ fused edge-softmax + aggregation + ELU + LayerNorm --------------------
template <int DOUT, bool OUT_BF16>
__global__ __launch_bounds__(256)
void gat_aggregate_ln_kernel(const int* __restrict__ rowptr,
                             const int* __restrict__ srcs,
                             const float* __restrict__ ssrc,
                             const float* __restrict__ sdst,
                             const float* __restrict__ Wx,
                             const float* __restrict__ g,
                             const float* __restrict__ b,
                             float* __restrict__ outf,
                             __nv_bfloat16* __restrict__ outb, int n)
{
    const int warp = (blockIdx.x * blockDim.x + threadIdx.x) >> 5;
    const int lane = threadIdx.x & 31;
    if (warp >= n) return;
    const int node = warp;
    const int begin = rowptr[node];
    const int end   = rowptr[node + 1];

    constexpr int PER = DOUT / 32;
    const int h = lane >> 3;

    const float4 sdv = *(const float4*)&sdst[node * 4];
    const float sd0 = sdv.x, sd1 = sdv.y, sd2 = sdv.z, sd3 = sdv.w;

    float d0 = 0.f, d1 = 0.f, d2 = 0.f, d3 = 0.f;
    for (int i = begin + lane; i < end; i += 32) {
        const int s = srcs[i];
        const float4 sv = *(const float4*)&ssrc[s * 4];
        float v;
        v = sv.x + sd0; v = v > 0.f ? v : 0.2f * v; d0 += expf(v);
        v = sv.y + sd1; v = v > 0.f ? v : 0.2f * v; d1 += expf(v);
        v = sv.z + sd2; v = v > 0.f ? v : 0.2f * v; d2 += expf(v);
        v = sv.w + sd3; v = v > 0.f ? v : 0.2f * v; d3 += expf(v);
    }
#pragma unroll
    for (int o = 16; o; o >>= 1) {
        d0 += __shfl_xor_sync(0xffffffffu, d0, o);
        d1 += __shfl_xor_sync(0xffffffffu, d1, o);
        d2 += __shfl_xor_sync(0xffffffffu, d2, o);
        d3 += __shfl_xor_sync(0xffffffffu, d3, o);
    }
    const float dh  = (h == 0) ? d0 : (h == 1) ? d1 : (h == 2) ? d2 : d3;
    const float sdh = (h == 0) ? sd0 : (h == 1) ? sd1 : (h == 2) ? sd2 : sd3;
    const float invd = 1.0f / (dh + 1e-8f);

    float acc[PER];
#pragma unroll
    for (int j = 0; j < PER; j++) acc[j] = 0.f;

    const int colbase = lane * PER;
    for (int i = begin; i < end; i++) {
        const int s = srcs[i];
        float e = ssrc[s * 4 + h] + sdh;
        e = e > 0.f ? e : 0.2f * e;
        const float alpha = expf(e) * invd;
        const float4* w = (const float4*)&Wx[(long long)s * DOUT + colbase];
#pragma unroll
        for (int j = 0; j < PER / 4; j++) {
            const float4 wv = w[j];
            acc[j * 4 + 0] = fmaf(alpha, wv.x, acc[j * 4 + 0]);
            acc[j * 4 + 1] = fmaf(alpha, wv.y, acc[j * 4 + 1]);
            acc[j * 4 + 2] = fmaf(alpha, wv.z, acc[j * 4 + 2]);
            acc[j * 4 + 3] = fmaf(alpha, wv.w, acc[j * 4 + 3]);
        }
    }

    float sum = 0.f, sumsq = 0.f;
#pragma unroll
    for (int j = 0; j < PER; j++) {
        float v = acc[j];
        v = (v > 0.f) ? v : expm1f(v);
        acc[j] = v;
        sum += v;
        sumsq = fmaf(v, v, sumsq);
    }
#pragma unroll
    for (int o = 16; o; o >>= 1) {
        sum   += __shfl_xor_sync(0xffffffffu, sum, o);
        sumsq += __shfl_xor_sync(0xffffffffu, sumsq, o);
    }
    const float inv = 1.0f / (float)DOUT;
    const float mu  = sum * inv;
    const float var = sumsq * inv - mu * mu;
    const float rs  = rsqrtf(var + 1e-5f);

    if (OUT_BF16) {
        union { __nv_bfloat16 b16[8]; uint4 v; } uhi, ulo;
#pragma unroll
        for (int j = 0; j < PER; j++) {
            const float fv = (acc[j] - mu) * rs * g[colbase + j] + b[colbase + j];
            split_bf16(fv, uhi.b16[j], ulo.b16[j]);
        }
        __nv_bfloat16* arow = outb + (size_t)node * (3 * DOUT);
        *(uint4*)&arow[colbase]            = uhi.v;   // sec 0: hi
        *(uint4*)&arow[DOUT + colbase]     = ulo.v;   // sec 1: lo
        *(uint4*)&arow[2 * DOUT + colbase] = uhi.v;   // sec 2: hi
    } else {
        float* orow = &outf[(long long)node * DOUT + colbase];
#pragma unroll
        for (int j = 0; j < PER / 4; j++) {
            const float4 gv = *(const float4*)&g[colbase + j * 4];
            const float4 bv = *(const float4*)&b[colbase + j * 4];
            float4 ov;
            ov.x = (acc[j * 4 + 0] - mu) * rs * gv.x + bv.x;
            ov.y = (acc[j * 4 + 1] - mu) * rs * gv.y + bv.y;
            ov.z = (acc[j * 4 + 2] - mu) * rs * gv.z + bv.z;
            ov.w = (acc[j * 4 + 3] - mu) * rs * gv.w + bv.w;
            *(float4*)&orow[j * 4] = ov;
        }
    }
}

// ---------------- host orchestration ------------------------------------------
extern "C" void kernel_launch(void* const* d_in, const int* in_sizes, int n_in,
                              void* d_out, int out_size)
{
    const float* x0 = (const float*)d_in[0];
    const int*   ei = (const int*)d_in[1];
    const float* W1 = (const float*)d_in[2];
    const float* a1 = (const float*)d_in[3];
    const float* g1 = (const float*)d_in[4];
    const float* b1 = (const float*)d_in[5];
    const float* W2 = (const float*)d_in[6];
    const float* a2 = (const float*)d_in[7];
    const float* g2 = (const float*)d_in[8];
    const float* b2 = (const float*)d_in[9];
    const float* W3 = (const float*)d_in[10];
    const float* a3 = (const float*)d_in[11];
    const float* g3 = (const float*)d_in[12];
    const float* b3 = (const float*)d_in[13];

    const int* src = ei;
    const int* dst = ei + NEDGES;

    float *wx, *ssrc, *sdst;
    __nv_bfloat16 *abf, *bbf;
    int *cnt, *rowptr, *fill, *srcs;
    cudaGetSymbolAddress((void**)&wx,     g_Wx);
    cudaGetSymbolAddress((void**)&abf,    g_Abf);
    cudaGetSymbolAddress((void**)&bbf,    g_Bbf);
    cudaGetSymbolAddress((void**)&ssrc,   g_ssrc);
    cudaGetSymbolAddress((void**)&sdst,   g_sdst);
    cudaGetSymbolAddress((void**)&cnt,    g_cnt);
    cudaGetSymbolAddress((void**)&rowptr, g_rowptr);
    cudaGetSymbolAddress((void**)&fill,   g_fill);
    cudaGetSymbolAddress((void**)&srcs,   g_srcs);

    cudaFuncSetAttribute(hmma_gemm_kernel,
                         cudaFuncAttributeMaxDynamicSharedMemorySize, GEMM_SMEM);

    float* outf = (float*)d_out;
    const int N = NNODES;
    const int mtiles = (N + 127) / 128;

    // ---- CSR build (edge_index identical for all 3 layers) ----
    cudaMemsetAsync(cnt, 0, NNODES * sizeof(int), 0);
    hist_kernel<<<(NEDGES + 255) / 256, 256>>>(dst, cnt, NEDGES);
    scan_kernel<<<1, 1024>>>(cnt, rowptr, fill, NNODES);
    scatter_kernel<<<(NEDGES + 255) / 256, 256>>>(src, dst, fill, srcs, NEDGES);

    // ---- layer 1: 523 -> 256 ----
    {
        convertA0_kernel<<<NNODES, 256>>>(x0, abf);
        convertW_kernel<<<256, 256>>>(W1, bbf, 523, KP1, 256);
        dim3 grid(256 / 128, mtiles);
        hmma_gemm_kernel<<<grid, 256, GEMM_SMEM>>>(abf, bbf, wx, N, 256, KP1);
        scores_kernel<<<(N * HEADS * 32 + 255) / 256, 256>>>(wx, a1, ssrc, sdst, N, 64);
        gat_aggregate_ln_kernel<256, true><<<(N * 32 + 255) / 256, 256>>>(
            rowptr, srcs, ssrc, sdst, wx, g1, b1, nullptr, abf, N);
    }
    // ---- layer 2: 256 -> 256 ----
    {
        convertW_kernel<<<256, 256>>>(W2, bbf, 256, KP2, 256);
        dim3 grid(256 / 128, mtiles);
        hmma_gemm_kernel<<<grid, 256, GEMM_SMEM>>>(abf, bbf, wx, N, 256, KP2);
        scores_kernel<<<(N * HEADS * 32 + 255) / 256, 256>>>(wx, a2, ssrc, sdst, N, 64);
        gat_aggregate_ln_kernel<256, true><<<(N * 32 + 255) / 256, 256>>>(
            rowptr, srcs, ssrc, sdst, wx, g2, b2, nullptr, abf, N);
    }
    // ---- layer 3: 256 -> 512, fp32 out ----
    {
        convertW_kernel<<<512, 256>>>(W3, bbf, 256, KP2, 512);
        dim3 grid(512 / 128, mtiles);
        hmma_gemm_kernel<<<grid, 256, GEMM_SMEM>>>(abf, bbf, wx, N, 512, KP2);
        scores_kernel<<<(N * HEADS * 32 + 255) / 256, 256>>>(wx, a3, ssrc, sdst, N, 128);
        gat_aggregate_ln_kernel<512, false><<<(N * 32 + 255) / 256, 256>>>(
            rowptr, srcs, ssrc, sdst, wx, g3, b3, outf, nullptr, N);
    }
}

// round 11
// speedup vs baseline: 1.8638x; 1.0184x over previous
#include <cuda_runtime.h>
#include <cuda_bf16.h>
#include <math.h>
#include <stdint.h>

#define NNODES 50000
#define NEDGES 400000
#define HEADS  4
#define KP1 1600   // padded K' for layer 1 (3*523=1569 -> 1600)
#define KP2 768    // K' for layers 2,3 (3*256)
#define NBLK ((NNODES + 1023) / 1024)   // 49 scan blocks

// ---------------- scratch (device globals; no allocation allowed) -------------
__device__ float g_Wx  [NNODES * 512];
__device__ __nv_bfloat16 g_Abf[(size_t)NNODES * KP1];
__device__ __nv_bfloat16 g_Bbf[512 * KP1];
__device__ float g_ssrc[NNODES * HEADS];
__device__ float g_sdst[NNODES * HEADS];
__device__ int g_cnt   [NNODES];
__device__ int g_rowptr[NNODES + 1];
__device__ int g_fill  [NNODES];
__device__ int g_srcs  [NEDGES];
__device__ int g_bsum  [64];

// ============================ PTX helpers (sm_80-level only) ===================
__device__ __forceinline__ uint32_t smem_u32(const void* p) {
    uint32_t a;
    asm("{ .reg .u64 t; cvta.to.shared.u64 t, %1; cvt.u32.u64 %0, t; }" : "=r"(a) : "l"(p));
    return a;
}
__device__ __forceinline__ void ldsm_x4(uint32_t& r0, uint32_t& r1,
                                        uint32_t& r2, uint32_t& r3, uint32_t addr) {
    asm volatile("ldmatrix.sync.aligned.m8n8.x4.shared.b16 {%0,%1,%2,%3}, [%4];"
                 : "=r"(r0), "=r"(r1), "=r"(r2), "=r"(r3) : "r"(addr));
}
__device__ __forceinline__ void mma_bf16(float* c, const uint32_t* a, const uint32_t* b) {
    asm volatile("mma.sync.aligned.m16n8k16.row.col.f32.bf16.bf16.f32 "
                 "{%0,%1,%2,%3}, {%4,%5,%6,%7}, {%8,%9}, {%0,%1,%2,%3};"
                 : "+f"(c[0]), "+f"(c[1]), "+f"(c[2]), "+f"(c[3])
                 : "r"(a[0]), "r"(a[1]), "r"(a[2]), "r"(a[3]), "r"(b[0]), "r"(b[1]));
}
__device__ __forceinline__ void cp_async16(uint32_t smem_addr, const void* g, bool pred) {
    const int sz = pred ? 16 : 0;
    asm volatile("cp.async.cg.shared.global [%0], [%1], 16, %2;"
                 :: "r"(smem_addr), "l"(g), "r"(sz));
}
#define CP_ASYNC_COMMIT() asm volatile("cp.async.commit_group;" ::: "memory")
#define CP_ASYNC_WAIT0()  asm volatile("cp.async.wait_group 0;"  ::: "memory")

// =============== HMMA GEMM: C[M,N] = A'[M,Kp] @ B'[N,Kp]^T ====================
#define ROWB 144
#define MATB (128 * ROWB)
#define BUFB (2 * MATB)
#define GEMM_SMEM (2 * BUFB)

__global__ __launch_bounds__(256, 2)
void hmma_gemm_kernel(const __nv_bfloat16* __restrict__ Aq,
                      const __nv_bfloat16* __restrict__ Bq,
                      float* __restrict__ C, int M, int N, int Kp)
{
    extern __shared__ __align__(16) char smem[];
    const uint32_t smem_base = smem_u32(smem);

    const int tid  = threadIdx.x;
    const int wid  = tid >> 5;
    const int lane = tid & 31;

    const int m0 = blockIdx.y * 128;
    const int n0 = blockIdx.x * 128;

    const int wm = (wid & 3) * 32;
    const int wn = (wid >> 2) * 64;

    const int lrow  = tid >> 1;
    const int lhalf = tid & 1;
    const bool a_ok = (m0 + lrow) < M;
    const __nv_bfloat16* Ag = Aq + (size_t)(a_ok ? (m0 + lrow) : 0) * Kp;
    const __nv_bfloat16* Bg = Bq + (size_t)(n0 + lrow) * Kp;

    const int sub = lane >> 3;
    const int srw = lane & 7;
    const uint32_t a_off = (uint32_t)(wm + (sub & 1) * 8 + srw) * ROWB + (sub >> 1) * 16;
    const uint32_t b_off = (uint32_t)(wn + (sub & 1) * 8 + srw) * ROWB + (sub >> 1) * 16;

    float acc[2][8][4];
#pragma unroll
    for (int i = 0; i < 2; i++)
#pragma unroll
        for (int j = 0; j < 8; j++)
#pragma unroll
            for (int r = 0; r < 4; r++) acc[i][j][r] = 0.f;

    const int ntiles = Kp / 64;

    auto issue = [&](int t, int buf) {
        const uint32_t sa = smem_base + buf * BUFB;
        const uint32_t sb = sa + MATB;
        const size_t gofs = (size_t)t * 64;
#pragma unroll
        for (int q = 0; q < 4; q++) {
            const int c16 = lhalf * 4 + q;
            const uint32_t sofs = (uint32_t)lrow * ROWB + c16 * 16;
            cp_async16(sa + sofs, (const char*)(Ag + gofs) + c16 * 16, a_ok);
            cp_async16(sb + sofs, (const char*)(Bg + gofs) + c16 * 16, true);
        }
        CP_ASYNC_COMMIT();
    };

    issue(0, 0);
    CP_ASYNC_WAIT0();
    __syncthreads();

    int buf = 0;
    for (int t = 0; t < ntiles; t++) {
        const bool more = (t + 1) < ntiles;
        if (more) issue(t + 1, buf ^ 1);

        const uint32_t sa = smem_base + buf * BUFB;
        const uint32_t sb = sa + MATB;
#pragma unroll
        for (int k0 = 0; k0 < 64; k0 += 16) {
            uint32_t af[2][4];
#pragma unroll
            for (int mi = 0; mi < 2; mi++)
                ldsm_x4(af[mi][0], af[mi][1], af[mi][2], af[mi][3],
                        sa + a_off + mi * 16 * ROWB + k0 * 2);
            uint32_t bf[8][2];
#pragma unroll
            for (int np = 0; np < 4; np++) {
                uint32_t r0, r1, r2, r3;
                ldsm_x4(r0, r1, r2, r3, sb + b_off + np * 16 * ROWB + k0 * 2);
                bf[2 * np][0] = r0; bf[2 * np + 1][0] = r1;
                bf[2 * np][1] = r2; bf[2 * np + 1][1] = r3;
            }
#pragma unroll
            for (int mi = 0; mi < 2; mi++)
#pragma unroll
                for (int ni = 0; ni < 8; ni++)
                    mma_bf16(acc[mi][ni], af[mi], bf[ni]);
        }

        if (more) CP_ASYNC_WAIT0();
        __syncthreads();
        buf ^= 1;
    }

    const int gid = lane >> 2;
    const int tig = lane & 3;
#pragma unroll
    for (int mi = 0; mi < 2; mi++) {
        const int m1 = m0 + wm + mi * 16 + gid;
        const int m2 = m1 + 8;
#pragma unroll
        for (int ni = 0; ni < 8; ni++) {
            const int nn = n0 + wn + ni * 8 + tig * 2;
            if (m1 < M) *(float2*)&C[(size_t)m1 * N + nn] =
                make_float2(acc[mi][ni][0], acc[mi][ni][1]);
            if (m2 < M) *(float2*)&C[(size_t)m2 * N + nn] =
                make_float2(acc[mi][ni][2], acc[mi][ni][3]);
        }
    }
}

// ====================== fp32 -> split bf16 conversions =========================
__device__ __forceinline__ void split_bf16(float x, __nv_bfloat16& hi, __nv_bfloat16& lo) {
    hi = __float2bfloat16(x);
    lo = __float2bfloat16(x - __bfloat162float(hi));
}

__global__ __launch_bounds__(256)
void convertA0_kernel(const float* __restrict__ x, __nv_bfloat16* __restrict__ out)
{
    const int m = blockIdx.x;
    const float* xr = x + (size_t)m * 523;
    __nv_bfloat16* orow = out + (size_t)m * KP1;
#pragma unroll
    for (int q = 0; q < 3; q++) {
        const int k = q * 256 + (int)threadIdx.x;
        if (k < 523) {
            __nv_bfloat16 hi, lo;
            split_bf16(xr[k], hi, lo);
            orow[k]        = hi;
            orow[523 + k]  = lo;
            orow[1046 + k] = hi;
        }
    }
    const int j = 1569 + (int)threadIdx.x;
    if (j < KP1) orow[j] = __float2bfloat16(0.0f);
}

__global__ __launch_bounds__(256)
void convertW_kernel(const float* __restrict__ W, __nv_bfloat16* __restrict__ out,
                     int K, int Kp, int N)
{
    const int n = blockIdx.x;
    __nv_bfloat16* orow = out + (size_t)n * Kp;
    for (int k = threadIdx.x; k < K; k += 256) {
        __nv_bfloat16 hi, lo;
        split_bf16(W[(size_t)k * N + n], hi, lo);
        orow[k]         = hi;
        orow[K + k]     = hi;
        orow[2 * K + k] = lo;
    }
    for (int j = 3 * K + threadIdx.x; j < Kp; j += 256)
        orow[j] = __float2bfloat16(0.0f);
}

// ---------------- CSR construction: parallel 3-phase scan ----------------------
__global__ void hist_kernel(const int* __restrict__ dst, int* __restrict__ cnt, int E)
{
    const int e = blockIdx.x * blockDim.x + threadIdx.x;
    if (e < E) atomicAdd(&cnt[dst[e]], 1);
}

// phase A: block-local inclusive scan; store local-incl in rowptr[i+1], totals in bsum
__global__ __launch_bounds__(1024)
void scanA_kernel(const int* __restrict__ cnt, int* __restrict__ rowptr,
                  int* __restrict__ bsum, int n)
{
    __shared__ int sh[1024];
    const int i = blockIdx.x * 1024 + (int)threadIdx.x;
    const int v = (i < n) ? cnt[i] : 0;
    sh[threadIdx.x] = v;
    __syncthreads();
#pragma unroll
    for (int o = 1; o < 1024; o <<= 1) {
        const int t = (threadIdx.x >= (unsigned)o) ? sh[threadIdx.x - o] : 0;
        __syncthreads();
        sh[threadIdx.x] += t;
        __syncthreads();
    }
    if (i < n) rowptr[i + 1] = sh[threadIdx.x];
    if (threadIdx.x == 1023) bsum[blockIdx.x] = sh[1023];
}

// phase B: single block scans the (<=64) block sums into exclusive offsets
__global__ __launch_bounds__(64)
void scanB_kernel(int* __restrict__ bsum, int nb)
{
    __shared__ int sh[64];
    const int t = (int)threadIdx.x;
    const int v = (t < nb) ? bsum[t] : 0;
    sh[t] = v;
    __syncthreads();
#pragma unroll
    for (int o = 1; o < 64; o <<= 1) {
        const int u = (t >= o) ? sh[t - o] : 0;
        __syncthreads();
        sh[t] += u;
        __syncthreads();
    }
    if (t < nb) bsum[t] = sh[t] - v;   // exclusive
}

// phase C: add block offsets; derive fill cursors; set rowptr[0]
__global__ void scanC_kernel(const int* __restrict__ cnt, int* __restrict__ rowptr,
                             int* __restrict__ fill, const int* __restrict__ bsum, int n)
{
    const int i = blockIdx.x * blockDim.x + threadIdx.x;
    if (i >= n) return;
    const int r = rowptr[i + 1] + bsum[i >> 10];
    rowptr[i + 1] = r;
    fill[i] = r - cnt[i];
    if (i == 0) rowptr[0] = 0;
}

__global__ void scatter_kernel(const int* __restrict__ src, const int* __restrict__ dst,
                               int* __restrict__ fill, int* __restrict__ srcs, int E)
{
    const int e = blockIdx.x * blockDim.x + threadIdx.x;
    if (e >= E) return;
    const int pos = atomicAdd(&fill[dst[e]], 1);
    srcs[pos] = src[e];
}

// ---------------- per-(node,head) attention scores ----------------------------
__global__ void scores_kernel(const float* __restrict__ Wx,
                              const float* __restrict__ a,
                              float* __restrict__ s_src, float* __restrict__ s_dst,
                              int n, int hd)
{
    const int warp = (blockIdx.x * blockDim.x + threadIdx.x) >> 5;
    const int lane = threadIdx.x & 31;
    if (warp >= n * HEADS) return;
    const int node = warp / HEADS;
    const int h    = warp % HEADS;
    const float* row = Wx + (long long)node * HEADS * hd + h * hd;
    float ss = 0.f, sd = 0.f;
    for (int d = lane; d < hd; d += 32) {
        const float v = row[d];
        ss = fmaf(v, a[d], ss);
        sd = fmaf(v, a[hd + d], sd);
    }
#pragma unroll
    for (int o = 16; o; o >>= 1) {
        ss += __shfl_xor_sync(0xffffffffu, ss, o);
        sd += __shfl_xor_sync(0xffffffffu, sd, o);
    }
    if (lane == 0) {
        s_src[node * HEADS + h] = ss;
        s_dst[node * HEADS + h] = sd;
    }
}

// ------ fused edge-softmax + aggregation + ELU + LayerNorm --------------------
template <int DOUT, bool OUT_BF16>
__global__ __launch_bounds__(256)
void gat_aggregate_ln_kernel(const int* __restrict__ rowptr,
                             const int* __restrict__ srcs,
                             const float* __restrict__ ssrc,
                             const float* __restrict__ sdst,
                             const float* __restrict__ Wx,
                             const float* __restrict__ g,
                             const float* __restrict__ b,
                             float* __restrict__ outf,
                             __nv_bfloat16* __restrict__ outb, int n)
{
    const int warp = (blockIdx.x * blockDim.x + threadIdx.x) >> 5;
    const int lane = threadIdx.x & 31;
    if (warp >= n) return;
    const int node = warp;
    const int begin = rowptr[node];
    const int end   = rowptr[node + 1];

    constexpr int PER = DOUT / 32;
    const int h = lane >> 3;

    const float4 sdv = *(const float4*)&sdst[node * 4];
    const float sd0 = sdv.x, sd1 = sdv.y, sd2 = sdv.z, sd3 = sdv.w;

    // pass 1: softmax denominators (all lanes end with d0..d3)
    float d0 = 0.f, d1 = 0.f, d2 = 0.f, d3 = 0.f;
    for (int i = begin + lane; i < end; i += 32) {
        const int s = srcs[i];
        const float4 sv = *(const float4*)&ssrc[s * 4];
        float v;
        v = sv.x + sd0; v = v > 0.f ? v : 0.2f * v; d0 += __expf(v);
        v = sv.y + sd1; v = v > 0.f ? v : 0.2f * v; d1 += __expf(v);
        v = sv.z + sd2; v = v > 0.f ? v : 0.2f * v; d2 += __expf(v);
        v = sv.w + sd3; v = v > 0.f ? v : 0.2f * v; d3 += __expf(v);
    }
#pragma unroll
    for (int o = 16; o; o >>= 1) {
        d0 += __shfl_xor_sync(0xffffffffu, d0, o);
        d1 += __shfl_xor_sync(0xffffffffu, d1, o);
        d2 += __shfl_xor_sync(0xffffffffu, d2, o);
        d3 += __shfl_xor_sync(0xffffffffu, d3, o);
    }
    const float inv0 = 1.0f / (d0 + 1e-8f);
    const float inv1 = 1.0f / (d1 + 1e-8f);
    const float inv2 = 1.0f / (d2 + 1e-8f);
    const float inv3 = 1.0f / (d3 + 1e-8f);

    float acc[PER];
#pragma unroll
    for (int j = 0; j < PER; j++) acc[j] = 0.f;

    // pass 2: alpha computed once per head (lanes 0..3), broadcast via shfl
    const int colbase = lane * PER;
    for (int i = begin; i < end; i++) {
        const int s = srcs[i];
        float al = 0.f;
        if (lane < 4) {
            const float sdh = (lane == 0) ? sd0 : (lane == 1) ? sd1
                            : (lane == 2) ? sd2 : sd3;
            const float ivh = (lane == 0) ? inv0 : (lane == 1) ? inv1
                            : (lane == 2) ? inv2 : inv3;
            float e = ssrc[s * 4 + lane] + sdh;
            e = e > 0.f ? e : 0.2f * e;
            al = __expf(e) * ivh;
        }
        const float alpha = __shfl_sync(0xffffffffu, al, h);
        const float4* w = (const float4*)&Wx[(long long)s * DOUT + colbase];
#pragma unroll
        for (int j = 0; j < PER / 4; j++) {
            const float4 wv = w[j];
            acc[j * 4 + 0] = fmaf(alpha, wv.x, acc[j * 4 + 0]);
            acc[j * 4 + 1] = fmaf(alpha, wv.y, acc[j * 4 + 1]);
            acc[j * 4 + 2] = fmaf(alpha, wv.z, acc[j * 4 + 2]);
            acc[j * 4 + 3] = fmaf(alpha, wv.w, acc[j * 4 + 3]);
        }
    }

    // ELU + LayerNorm
    float sum = 0.f, sumsq = 0.f;
#pragma unroll
    for (int j = 0; j < PER; j++) {
        float v = acc[j];
        v = (v > 0.f) ? v : (__expf(v) - 1.0f);
        acc[j] = v;
        sum += v;
        sumsq = fmaf(v, v, sumsq);
    }
#pragma unroll
    for (int o = 16; o; o >>= 1) {
        sum   += __shfl_xor_sync(0xffffffffu, sum, o);
        sumsq += __shfl_xor_sync(0xffffffffu, sumsq, o);
    }
    const float inv = 1.0f / (float)DOUT;
    const float mu  = sum * inv;
    const float var = sumsq * inv - mu * mu;
    const float rs  = rsqrtf(var + 1e-5f);

    if (OUT_BF16) {
        union { __nv_bfloat16 b16[8]; uint4 v; } uhi, ulo;
#pragma unroll
        for (int j = 0; j < PER; j++) {
            const float fv = (acc[j] - mu) * rs * g[colbase + j] + b[colbase + j];
            split_bf16(fv, uhi.b16[j], ulo.b16[j]);
        }
        __nv_bfloat16* arow = outb + (size_t)node * (3 * DOUT);
        *(uint4*)&arow[colbase]            = uhi.v;
        *(uint4*)&arow[DOUT + colbase]     = ulo.v;
        *(uint4*)&arow[2 * DOUT + colbase] = uhi.v;
    } else {
        float* orow = &outf[(long long)node * DOUT + colbase];
#pragma unroll
        for (int j = 0; j < PER / 4; j++) {
            const float4 gv = *(const float4*)&g[colbase + j * 4];
            const float4 bv = *(const float4*)&b[colbase + j * 4];
            float4 ov;
            ov.x = (acc[j * 4 + 0] - mu) * rs * gv.x + bv.x;
            ov.y = (acc[j * 4 + 1] - mu) * rs * gv.y + bv.y;
            ov.z = (acc[j * 4 + 2] - mu) * rs * gv.z + bv.z;
            ov.w = (acc[j * 4 + 3] - mu) * rs * gv.w + bv.w;
            *(float4*)&orow[j * 4] = ov;
        }
    }
}

// ---------------- host orchestration ------------------------------------------
extern "C" void kernel_launch(void* const* d_in, const int* in_sizes, int n_in,
                              void* d_out, int out_size)
{
    const float* x0 = (const float*)d_in[0];
    const int*   ei = (const int*)d_in[1];
    const float* W1 = (const float*)d_in[2];
    const float* a1 = (const float*)d_in[3];
    const float* g1 = (const float*)d_in[4];
    const float* b1 = (const float*)d_in[5];
    const float* W2 = (const float*)d_in[6];
    const float* a2 = (const float*)d_in[7];
    const float* g2 = (const float*)d_in[8];
    const float* b2 = (const float*)d_in[9];
    const float* W3 = (const float*)d_in[10];
    const float* a3 = (const float*)d_in[11];
    const float* g3 = (const float*)d_in[12];
    const float* b3 = (const float*)d_in[13];

    const int* src = ei;
    const int* dst = ei + NEDGES;

    float *wx, *ssrc, *sdst;
    __nv_bfloat16 *abf, *bbf;
    int *cnt, *rowptr, *fill, *srcs, *bsum;
    cudaGetSymbolAddress((void**)&wx,     g_Wx);
    cudaGetSymbolAddress((void**)&abf,    g_Abf);
    cudaGetSymbolAddress((void**)&bbf,    g_Bbf);
    cudaGetSymbolAddress((void**)&ssrc,   g_ssrc);
    cudaGetSymbolAddress((void**)&sdst,   g_sdst);
    cudaGetSymbolAddress((void**)&cnt,    g_cnt);
    cudaGetSymbolAddress((void**)&rowptr, g_rowptr);
    cudaGetSymbolAddress((void**)&fill,   g_fill);
    cudaGetSymbolAddress((void**)&srcs,   g_srcs);
    cudaGetSymbolAddress((void**)&bsum,   g_bsum);

    cudaFuncSetAttribute(hmma_gemm_kernel,
                         cudaFuncAttributeMaxDynamicSharedMemorySize, GEMM_SMEM);

    float* outf = (float*)d_out;
    const int N = NNODES;
    const int mtiles = (N + 127) / 128;

    // ---- CSR build (parallel scan) ----
    cudaMemsetAsync(cnt, 0, NNODES * sizeof(int), 0);
    hist_kernel<<<(NEDGES + 255) / 256, 256>>>(dst, cnt, NEDGES);
    scanA_kernel<<<NBLK, 1024>>>(cnt, rowptr, bsum, NNODES);
    scanB_kernel<<<1, 64>>>(bsum, NBLK);
    scanC_kernel<<<(NNODES + 255) / 256, 256>>>(cnt, rowptr, fill, bsum, NNODES);
    scatter_kernel<<<(NEDGES + 255) / 256, 256>>>(src, dst, fill, srcs, NEDGES);

    // ---- layer 1: 523 -> 256 ----
    {
        convertA0_kernel<<<NNODES, 256>>>(x0, abf);
        convertW_kernel<<<256, 256>>>(W1, bbf, 523, KP1, 256);
        dim3 grid(256 / 128, mtiles);
        hmma_gemm_kernel<<<grid, 256, GEMM_SMEM>>>(abf, bbf, wx, N, 256, KP1);
        scores_kernel<<<(N * HEADS * 32 + 255) / 256, 256>>>(wx, a1, ssrc, sdst, N, 64);
        gat_aggregate_ln_kernel<256, true><<<(N * 32 + 255) / 256, 256>>>(
            rowptr, srcs, ssrc, sdst, wx, g1, b1, nullptr, abf, N);
    }
    // ---- layer 2: 256 -> 256 ----
    {
        convertW_kernel<<<256, 256>>>(W2, bbf, 256, KP2, 256);
        dim3 grid(256 / 128, mtiles);
        hmma_gemm_kernel<<<grid, 256, GEMM_SMEM>>>(abf, bbf, wx, N, 256, KP2);
        scores_kernel<<<(N * HEADS * 32 + 255) / 256, 256>>>(wx, a2, ssrc, sdst, N, 64);
        gat_aggregate_ln_kernel<256, true><<<(N * 32 + 255) / 256, 256>>>(
            rowptr, srcs, ssrc, sdst, wx, g2, b2, nullptr, abf, N);
    }
    // ---- layer 3: 256 -> 512, fp32 out ----
    {
        convertW_kernel<<<512, 256>>>(W3, bbf, 256, KP2, 512);
        dim3 grid(512 / 128, mtiles);
        hmma_gemm_kernel<<<grid, 256, GEMM_SMEM>>>(abf, bbf, wx, N, 512, KP2);
        scores_kernel<<<(N * HEADS * 32 + 255) / 256, 256>>>(wx, a3, ssrc, sdst, N, 128);
        gat_aggregate_ln_kernel<512, false><<<(N * 32 + 255) / 256, 256>>>(
            rowptr, srcs, ssrc, sdst, wx, g3, b3, outf, nullptr, N);
    }
}

// round 14
// speedup vs baseline: 2.0051x; 1.0758x over previous
#include <cuda_runtime.h>
#include <cuda_bf16.h>
#include <math.h>
#include <stdint.h>

#define NNODES 50000
#define NEDGES 400000
#define HEADS  4
#define KP1 1600   // padded K' for layer 1: sections at 0 / 524 / 1048 (K=523 + 1 pad)
#define SEC1 524
#define KP2 768    // K' for layers 2,3 (3*256)
#define NBLK ((NNODES + 1023) / 1024)

// ---------------- scratch (device globals; no allocation allowed) -------------
__device__ float g_Wx  [NNODES * 512];
__device__ __nv_bfloat16 g_Abf[(size_t)NNODES * KP1];
__device__ __nv_bfloat16 g_Bbf[512 * KP1];
__device__ float g_ssrc[NNODES * HEADS];
__device__ float g_sdst[NNODES * HEADS];
__device__ int g_cnt   [NNODES];
__device__ int g_rowptr[NNODES + 1];
__device__ int g_fill  [NNODES];
__device__ int g_srcs  [NEDGES];
__device__ int g_bsum  [64];

// ============================ PTX helpers (sm_80-level only) ===================
__device__ __forceinline__ uint32_t smem_u32(const void* p) {
    uint32_t a;
    asm("{ .reg .u64 t; cvta.to.shared.u64 t, %1; cvt.u32.u64 %0, t; }" : "=r"(a) : "l"(p));
    return a;
}
__device__ __forceinline__ void ldsm_x4(uint32_t& r0, uint32_t& r1,
                                        uint32_t& r2, uint32_t& r3, uint32_t addr) {
    asm volatile("ldmatrix.sync.aligned.m8n8.x4.shared.b16 {%0,%1,%2,%3}, [%4];"
                 : "=r"(r0), "=r"(r1), "=r"(r2), "=r"(r3) : "r"(addr));
}
__device__ __forceinline__ void mma_bf16(float* c, const uint32_t* a, const uint32_t* b) {
    asm volatile("mma.sync.aligned.m16n8k16.row.col.f32.bf16.bf16.f32 "
                 "{%0,%1,%2,%3}, {%4,%5,%6,%7}, {%8,%9}, {%0,%1,%2,%3};"
                 : "+f"(c[0]), "+f"(c[1]), "+f"(c[2]), "+f"(c[3])
                 : "r"(a[0]), "r"(a[1]), "r"(a[2]), "r"(a[3]), "r"(b[0]), "r"(b[1]));
}
__device__ __forceinline__ void cp_async16(uint32_t smem_addr, const void* g, bool pred) {
    const int sz = pred ? 16 : 0;
    asm volatile("cp.async.cg.shared.global [%0], [%1], 16, %2;"
                 :: "r"(smem_addr), "l"(g), "r"(sz));
}
#define CP_ASYNC_COMMIT() asm volatile("cp.async.commit_group;" ::: "memory")
#define CP_ASYNC_WAIT0()  asm volatile("cp.async.wait_group 0;"  ::: "memory")

// === HMMA GEMM + fused attention scores =======================================
// C[M,N] = A'[M,Kp] @ B'[N,Kp]^T ; also ssrc/sdst[m,h] = dot(C_row_head, av)
#define ROWB 144
#define MATB (128 * ROWB)
#define BUFB (2 * MATB)
#define GEMM_SMEM (2 * BUFB)

__global__ __launch_bounds__(256, 2)
void hmma_gemm_kernel(const __nv_bfloat16* __restrict__ Aq,
                      const __nv_bfloat16* __restrict__ Bq,
                      float* __restrict__ C, int M, int N, int Kp,
                      const float* __restrict__ av, int hd,
                      float* __restrict__ ssrc, float* __restrict__ sdst)
{
    extern __shared__ __align__(16) char smem[];
    const uint32_t smem_base = smem_u32(smem);

    const int tid  = threadIdx.x;
    const int wid  = tid >> 5;
    const int lane = tid & 31;

    const int m0 = blockIdx.y * 128;
    const int n0 = blockIdx.x * 128;

    const int wm = (wid & 3) * 32;
    const int wn = (wid >> 2) * 64;

    const int lrow  = tid >> 1;
    const int lhalf = tid & 1;
    const bool a_ok = (m0 + lrow) < M;
    const __nv_bfloat16* Ag = Aq + (size_t)(a_ok ? (m0 + lrow) : 0) * Kp;
    const __nv_bfloat16* Bg = Bq + (size_t)(n0 + lrow) * Kp;

    const int sub = lane >> 3;
    const int srw = lane & 7;
    const uint32_t a_off = (uint32_t)(wm + (sub & 1) * 8 + srw) * ROWB + (sub >> 1) * 16;
    const uint32_t b_off = (uint32_t)(wn + (sub & 1) * 8 + srw) * ROWB + (sub >> 1) * 16;

    float acc[2][8][4];
#pragma unroll
    for (int i = 0; i < 2; i++)
#pragma unroll
        for (int j = 0; j < 8; j++)
#pragma unroll
            for (int r = 0; r < 4; r++) acc[i][j][r] = 0.f;

    const int ntiles = Kp / 64;

    auto issue = [&](int t, int buf) {
        const uint32_t sa = smem_base + buf * BUFB;
        const uint32_t sb = sa + MATB;
        const size_t gofs = (size_t)t * 64;
#pragma unroll
        for (int q = 0; q < 4; q++) {
            const int c16 = lhalf * 4 + q;
            const uint32_t sofs = (uint32_t)lrow * ROWB + c16 * 16;
            cp_async16(sa + sofs, (const char*)(Ag + gofs) + c16 * 16, a_ok);
            cp_async16(sb + sofs, (const char*)(Bg + gofs) + c16 * 16, true);
        }
        CP_ASYNC_COMMIT();
    };

    issue(0, 0);
    CP_ASYNC_WAIT0();
    __syncthreads();

    int buf = 0;
    for (int t = 0; t < ntiles; t++) {
        const bool more = (t + 1) < ntiles;
        if (more) issue(t + 1, buf ^ 1);

        const uint32_t sa = smem_base + buf * BUFB;
        const uint32_t sb = sa + MATB;
#pragma unroll
        for (int k0 = 0; k0 < 64; k0 += 16) {
            uint32_t af[2][4];
#pragma unroll
            for (int mi = 0; mi < 2; mi++)
                ldsm_x4(af[mi][0], af[mi][1], af[mi][2], af[mi][3],
                        sa + a_off + mi * 16 * ROWB + k0 * 2);
            uint32_t bf[8][2];
#pragma unroll
            for (int np = 0; np < 4; np++) {
                uint32_t r0, r1, r2, r3;
                ldsm_x4(r0, r1, r2, r3, sb + b_off + np * 16 * ROWB + k0 * 2);
                bf[2 * np][0] = r0; bf[2 * np + 1][0] = r1;
                bf[2 * np][1] = r2; bf[2 * np + 1][1] = r3;
            }
#pragma unroll
            for (int mi = 0; mi < 2; mi++)
#pragma unroll
                for (int ni = 0; ni < 8; ni++)
                    mma_bf16(acc[mi][ni], af[mi], bf[ni]);
        }

        if (more) CP_ASYNC_WAIT0();
        __syncthreads();
        buf ^= 1;
    }

    const int gid = lane >> 2;
    const int tig = lane & 3;

    // ---- C store + fused per-head score partials ----
    // For hd=64 each warp's 64-col slice is one full head; for hd=128 it is half
    // a head and warps wid and wid+4 (same wm) must combine partials via smem.
    const int cmask = hd - 1;
    float aS[4] = {0.f, 0.f, 0.f, 0.f};
    float aD[4] = {0.f, 0.f, 0.f, 0.f};

#pragma unroll
    for (int mi = 0; mi < 2; mi++) {
        const int m1 = m0 + wm + mi * 16 + gid;
        const int m2 = m1 + 8;
#pragma unroll
        for (int ni = 0; ni < 8; ni++) {
            const int nn = n0 + wn + ni * 8 + tig * 2;
            const int c  = nn & cmask;
            const float as0 = av[c], as1 = av[c + 1];
            const float ad0 = av[hd + c], ad1 = av[hd + c + 1];
            aS[mi * 2]     += acc[mi][ni][0] * as0 + acc[mi][ni][1] * as1;
            aD[mi * 2]     += acc[mi][ni][0] * ad0 + acc[mi][ni][1] * ad1;
            aS[mi * 2 + 1] += acc[mi][ni][2] * as0 + acc[mi][ni][3] * as1;
            aD[mi * 2 + 1] += acc[mi][ni][2] * ad0 + acc[mi][ni][3] * ad1;
            if (m1 < M) *(float2*)&C[(size_t)m1 * N + nn] =
                make_float2(acc[mi][ni][0], acc[mi][ni][1]);
            if (m2 < M) *(float2*)&C[(size_t)m2 * N + nn] =
                make_float2(acc[mi][ni][2], acc[mi][ni][3]);
        }
    }
#pragma unroll
    for (int r = 0; r < 4; r++) {
        aS[r] += __shfl_xor_sync(0xffffffffu, aS[r], 1);
        aS[r] += __shfl_xor_sync(0xffffffffu, aS[r], 2);
        aD[r] += __shfl_xor_sync(0xffffffffu, aD[r], 1);
        aD[r] += __shfl_xor_sync(0xffffffffu, aD[r], 2);
    }

    if (hd == 64) {
        const int head = (n0 + wn) / 64;
        if (tig == 0) {
#pragma unroll
            for (int mi = 0; mi < 2; mi++) {
                const int m1 = m0 + wm + mi * 16 + gid;
                const int m2 = m1 + 8;
                if (m1 < M) {
                    ssrc[m1 * 4 + head] = aS[mi * 2];
                    sdst[m1 * 4 + head] = aD[mi * 2];
                }
                if (m2 < M) {
                    ssrc[m2 * 4 + head] = aS[mi * 2 + 1];
                    sdst[m2 * 4 + head] = aD[mi * 2 + 1];
                }
            }
        }
    } else {
        // hd == 128: combine partials of warp pairs (wid, wid+4) via smem.
        float* sbuf = (float*)smem;   // tile smem free after last main-loop sync
        __syncthreads();
        if (wid >= 4 && tig == 0) {
            const int base = (((wid & 3) * 8 + gid) * 4) * 2;
#pragma unroll
            for (int r = 0; r < 4; r++) {
                sbuf[base + r * 2]     = aS[r];
                sbuf[base + r * 2 + 1] = aD[r];
            }
        }
        __syncthreads();
        if (wid < 4 && tig == 0) {
            const int base = ((wid * 8 + gid) * 4) * 2;
#pragma unroll
            for (int r = 0; r < 4; r++) {
                aS[r] += sbuf[base + r * 2];
                aD[r] += sbuf[base + r * 2 + 1];
            }
            const int head = n0 / 128;
#pragma unroll
            for (int mi = 0; mi < 2; mi++) {
                const int m1 = m0 + wm + mi * 16 + gid;
                const int m2 = m1 + 8;
                if (m1 < M) {
                    ssrc[m1 * 4 + head] = aS[mi * 2];
                    sdst[m1 * 4 + head] = aD[mi * 2];
                }
                if (m2 < M) {
                    ssrc[m2 * 4 + head] = aS[mi * 2 + 1];
                    sdst[m2 * 4 + head] = aD[mi * 2 + 1];
                }
            }
        }
    }
}

// ====================== fp32 -> split bf16 conversions =========================
__device__ __forceinline__ void split_bf16(float x, __nv_bfloat16& hi, __nv_bfloat16& lo) {
    hi = __float2bfloat16(x);
    lo = __float2bfloat16(x - __bfloat162float(hi));
}
__device__ __forceinline__ uint32_t pack_bf2(__nv_bfloat16 a, __nv_bfloat16 b) {
    __nv_bfloat162 t = __halves2bfloat162(a, b);
    return *(uint32_t*)&t;
}

// A' layer 1: sections [hi | lo | hi] at 0 / 524 / 1048; pads zeroed.
// A rows only 4B-aligned (K=523 odd) -> scalar loads, packed u32 stores.
__global__ __launch_bounds__(256)
void convertA0_kernel(const float* __restrict__ x, __nv_bfloat16* __restrict__ out)
{
    const int m = blockIdx.x;
    const float* xr = x + (size_t)m * 523;
    __nv_bfloat16* orow = out + (size_t)m * KP1;
    uint32_t* o32 = (uint32_t*)orow;
    const int t = (int)threadIdx.x;
#pragma unroll
    for (int q = 0; q < 2; q++) {
        const int p = q * 256 + t;       // pair index, 261 pairs cover k=0..521
        if (p < 261) {
            const float x0 = xr[p * 2];
            const float x1 = xr[p * 2 + 1];
            __nv_bfloat16 h0, l0, h1, l1;
            split_bf16(x0, h0, l0);
            split_bf16(x1, h1, l1);
            const uint32_t hp = pack_bf2(h0, h1);
            const uint32_t lp = pack_bf2(l0, l1);
            o32[p]                  = hp;
            o32[SEC1 / 2 + p]       = lp;
            o32[2 * (SEC1 / 2) + p] = hp;
        }
    }
    if (t == 0) {
        __nv_bfloat16 hi, lo;
        split_bf16(xr[522], hi, lo);
        orow[522]            = hi;
        orow[523]            = __float2bfloat16(0.f);
        orow[SEC1 + 522]     = lo;
        orow[SEC1 + 523]     = __float2bfloat16(0.f);
        orow[2 * SEC1 + 522] = hi;
        orow[2 * SEC1 + 523] = __float2bfloat16(0.f);
    }
    const int j = 3 * SEC1 + t;          // 1572..1599
    if (j < KP1) orow[j] = __float2bfloat16(0.f);
}

// B' layer 1 from W[523,N]: sections [hi | hi | lo] at 0 / 524 / 1048, pads zero
__global__ __launch_bounds__(256)
void convertW1_kernel(const float* __restrict__ W, __nv_bfloat16* __restrict__ out, int N)
{
    const int n = blockIdx.x;
    __nv_bfloat16* orow = out + (size_t)n * KP1;
    for (int k = threadIdx.x; k < 523; k += 256) {
        __nv_bfloat16 hi, lo;
        split_bf16(W[(size_t)k * N + n], hi, lo);
        orow[k]            = hi;
        orow[SEC1 + k]     = hi;
        orow[2 * SEC1 + k] = lo;
    }
    if (threadIdx.x == 0) {
        orow[523]            = __float2bfloat16(0.f);
        orow[SEC1 + 523]     = __float2bfloat16(0.f);
        orow[2 * SEC1 + 523] = __float2bfloat16(0.f);
    }
    for (int j = 3 * SEC1 + threadIdx.x; j < KP1; j += 256)
        orow[j] = __float2bfloat16(0.f);
}

// B' layers 2/3 from W[256,N]: sections [hi | hi | lo] at 0 / 256 / 512
__global__ __launch_bounds__(256)
void convertW_kernel(const float* __restrict__ W, __nv_bfloat16* __restrict__ out, int N)
{
    const int n = blockIdx.x;
    __nv_bfloat16* orow = out + (size_t)n * KP2;
    const int k = (int)threadIdx.x;
    __nv_bfloat16 hi, lo;
    split_bf16(W[(size_t)k * N + n], hi, lo);
    orow[k]       = hi;
    orow[256 + k] = hi;
    orow[512 + k] = lo;
}

// ---------------- CSR construction: parallel 3-phase scan ----------------------
__global__ void hist_kernel(const int* __restrict__ dst, int* __restrict__ cnt, int E)
{
    const int e = blockIdx.x * blockDim.x + threadIdx.x;
    if (e < E) atomicAdd(&cnt[dst[e]], 1);
}

__global__ __launch_bounds__(1024)
void scanA_kernel(const int* __restrict__ cnt, int* __restrict__ rowptr,
                  int* __restrict__ bsum, int n)
{
    __shared__ int sh[1024];
    const int i = blockIdx.x * 1024 + (int)threadIdx.x;
    const int v = (i < n) ? cnt[i] : 0;
    sh[threadIdx.x] = v;
    __syncthreads();
#pragma unroll
    for (int o = 1; o < 1024; o <<= 1) {
        const int t = (threadIdx.x >= (unsigned)o) ? sh[threadIdx.x - o] : 0;
        __syncthreads();
        sh[threadIdx.x] += t;
        __syncthreads();
    }
    if (i < n) rowptr[i + 1] = sh[threadIdx.x];
    if (threadIdx.x == 1023) bsum[blockIdx.x] = sh[1023];
}

__global__ __launch_bounds__(64)
void scanB_kernel(int* __restrict__ bsum, int nb)
{
    __shared__ int sh[64];
    const int t = (int)threadIdx.x;
    const int v = (t < nb) ? bsum[t] : 0;
    sh[t] = v;
    __syncthreads();
#pragma unroll
    for (int o = 1; o < 64; o <<= 1) {
        const int u = (t >= o) ? sh[t - o] : 0;
        __syncthreads();
        sh[t] += u;
        __syncthreads();
    }
    if (t < nb) bsum[t] = sh[t] - v;
}

__global__ void scanC_kernel(const int* __restrict__ cnt, int* __restrict__ rowptr,
                             int* __restrict__ fill, const int* __restrict__ bsum, int n)
{
    const int i = blockIdx.x * blockDim.x + threadIdx.x;
    if (i >= n) return;
    const int r = rowptr[i + 1] + bsum[i >> 10];
    rowptr[i + 1] = r;
    fill[i] = r - cnt[i];
    if (i == 0) rowptr[0] = 0;
}

__global__ void scatter_kernel(const int* __restrict__ src, const int* __restrict__ dst,
                               int* __restrict__ fill, int* __restrict__ srcs, int E)
{
    const int e = blockIdx.x * blockDim.x + threadIdx.x;
    if (e >= E) return;
    const int pos = atomicAdd(&fill[dst[e]], 1);
    srcs[pos] = src[e];
}

// ------ fused edge-softmax + aggregation + ELU + LayerNorm --------------------
template <int DOUT, bool OUT_BF16>
__global__ __launch_bounds__(256)
void gat_aggregate_ln_kernel(const int* __restrict__ rowptr,
                             const int* __restrict__ srcs,
                             const float* __restrict__ ssrc,
                             const float* __restrict__ sdst,
                             const float* __restrict__ Wx,
                             const float* __restrict__ g,
                             const float* __restrict__ b,
                             float* __restrict__ outf,
                             __nv_bfloat16* __restrict__ outb, int n)
{
    const int warp = (blockIdx.x * blockDim.x + threadIdx.x) >> 5;
    const int lane = threadIdx.x & 31;
    if (warp >= n) return;
    const int node = warp;
    const int begin = rowptr[node];
    const int end   = rowptr[node + 1];

    constexpr int PER = DOUT / 32;
    const int h = lane >> 3;

    const float4 sdv = *(const float4*)&sdst[node * 4];
    const float sd0 = sdv.x, sd1 = sdv.y, sd2 = sdv.z, sd3 = sdv.w;

    float d0 = 0.f, d1 = 0.f, d2 = 0.f, d3 = 0.f;
    for (int i = begin + lane; i < end; i += 32) {
        const int s = srcs[i];
        const float4 sv = *(const float4*)&ssrc[s * 4];
        float v;
        v = sv.x + sd0; v = v > 0.f ? v : 0.2f * v; d0 += __expf(v);
        v = sv.y + sd1; v = v > 0.f ? v : 0.2f * v; d1 += __expf(v);
        v = sv.z + sd2; v = v > 0.f ? v : 0.2f * v; d2 += __expf(v);
        v = sv.w + sd3; v = v > 0.f ? v : 0.2f * v; d3 += __expf(v);
    }
#pragma unroll
    for (int o = 16; o; o >>= 1) {
        d0 += __shfl_xor_sync(0xffffffffu, d0, o);
        d1 += __shfl_xor_sync(0xffffffffu, d1, o);
        d2 += __shfl_xor_sync(0xffffffffu, d2, o);
        d3 += __shfl_xor_sync(0xffffffffu, d3, o);
    }
    const float inv0 = 1.0f / (d0 + 1e-8f);
    const float inv1 = 1.0f / (d1 + 1e-8f);
    const float inv2 = 1.0f / (d2 + 1e-8f);
    const float inv3 = 1.0f / (d3 + 1e-8f);

    float acc[PER];
#pragma unroll
    for (int j = 0; j < PER; j++) acc[j] = 0.f;

    const int colbase = lane * PER;
    for (int i = begin; i < end; i++) {
        const int s = srcs[i];
        float al = 0.f;
        if (lane < 4) {
            const float sdh = (lane == 0) ? sd0 : (lane == 1) ? sd1
                            : (lane == 2) ? sd2 : sd3;
            const float ivh = (lane == 0) ? inv0 : (lane == 1) ? inv1
                            : (lane == 2) ? inv2 : inv3;
            float e = ssrc[s * 4 + lane] + sdh;
            e = e > 0.f ? e : 0.2f * e;
            al = __expf(e) * ivh;
        }
        const float alpha = __shfl_sync(0xffffffffu, al, h);
        const float4* w = (const float4*)&Wx[(long long)s * DOUT + colbase];
#pragma unroll
        for (int j = 0; j < PER / 4; j++) {
            const float4 wv = w[j];
            acc[j * 4 + 0] = fmaf(alpha, wv.x, acc[j * 4 + 0]);
            acc[j * 4 + 1] = fmaf(alpha, wv.y, acc[j * 4 + 1]);
            acc[j * 4 + 2] = fmaf(alpha, wv.z, acc[j * 4 + 2]);
            acc[j * 4 + 3] = fmaf(alpha, wv.w, acc[j * 4 + 3]);
        }
    }

    float sum = 0.f, sumsq = 0.f;
#pragma unroll
    for (int j = 0; j < PER; j++) {
        float v = acc[j];
        v = (v > 0.f) ? v : (__expf(v) - 1.0f);
        acc[j] = v;
        sum += v;
        sumsq = fmaf(v, v, sumsq);
    }
#pragma unroll
    for (int o = 16; o; o >>= 1) {
        sum   += __shfl_xor_sync(0xffffffffu, sum, o);
        sumsq += __shfl_xor_sync(0xffffffffu, sumsq, o);
    }
    const float inv = 1.0f / (float)DOUT;
    const float mu  = sum * inv;
    const float var = sumsq * inv - mu * mu;
    const float rs  = rsqrtf(var + 1e-5f);

    if (OUT_BF16) {
        union { __nv_bfloat16 b16[8]; uint4 v; } uhi, ulo;
#pragma unroll
        for (int j = 0; j < PER; j++) {
            const float fv = (acc[j] - mu) * rs * g[colbase + j] + b[colbase + j];
            split_bf16(fv, uhi.b16[j], ulo.b16[j]);
        }
        __nv_bfloat16* arow = outb + (size_t)node * (3 * DOUT);
        *(uint4*)&arow[colbase]            = uhi.v;
        *(uint4*)&arow[DOUT + colbase]     = ulo.v;
        *(uint4*)&arow[2 * DOUT + colbase] = uhi.v;
    } else {
        float* orow = &outf[(long long)node * DOUT + colbase];
#pragma unroll
        for (int j = 0; j < PER / 4; j++) {
            const float4 gv = *(const float4*)&g[colbase + j * 4];
            const float4 bv = *(const float4*)&b[colbase + j * 4];
            float4 ov;
            ov.x = (acc[j * 4 + 0] - mu) * rs * gv.x + bv.x;
            ov.y = (acc[j * 4 + 1] - mu) * rs * gv.y + bv.y;
            ov.z = (acc[j * 4 + 2] - mu) * rs * gv.z + bv.z;
            ov.w = (acc[j * 4 + 3] - mu) * rs * gv.w + bv.w;
            *(float4*)&orow[j * 4] = ov;
        }
    }
}

// ---------------- host orchestration ------------------------------------------
extern "C" void kernel_launch(void* const* d_in, const int* in_sizes, int n_in,
                              void* d_out, int out_size)
{
    const float* x0 = (const float*)d_in[0];
    const int*   ei = (const int*)d_in[1];
    const float* W1 = (const float*)d_in[2];
    const float* a1 = (const float*)d_in[3];
    const float* g1 = (const float*)d_in[4];
    const float* b1 = (const float*)d_in[5];
    const float* W2 = (const float*)d_in[6];
    const float* a2 = (const float*)d_in[7];
    const float* g2 = (const float*)d_in[8];
    const float* b2 = (const float*)d_in[9];
    const float* W3 = (const float*)d_in[10];
    const float* a3 = (const float*)d_in[11];
    const float* g3 = (const float*)d_in[12];
    const float* b3 = (const float*)d_in[13];

    const int* src = ei;
    const int* dst = ei + NEDGES;

    float *wx, *ssrc, *sdst;
    __nv_bfloat16 *abf, *bbf;
    int *cnt, *rowptr, *fill, *srcs, *bsum;
    cudaGetSymbolAddress((void**)&wx,     g_Wx);
    cudaGetSymbolAddress((void**)&abf,    g_Abf);
    cudaGetSymbolAddress((void**)&bbf,    g_Bbf);
    cudaGetSymbolAddress((void**)&ssrc,   g_ssrc);
    cudaGetSymbolAddress((void**)&sdst,   g_sdst);
    cudaGetSymbolAddress((void**)&cnt,    g_cnt);
    cudaGetSymbolAddress((void**)&rowptr, g_rowptr);
    cudaGetSymbolAddress((void**)&fill,   g_fill);
    cudaGetSymbolAddress((void**)&srcs,   g_srcs);
    cudaGetSymbolAddress((void**)&bsum,   g_bsum);

    cudaFuncSetAttribute(hmma_gemm_kernel,
                         cudaFuncAttributeMaxDynamicSharedMemorySize, GEMM_SMEM);

    float* outf = (float*)d_out;
    const int N = NNODES;
    const int mtiles = (N + 127) / 128;

    // ---- CSR build ----
    cudaMemsetAsync(cnt, 0, NNODES * sizeof(int), 0);
    hist_kernel<<<(NEDGES + 255) / 256, 256>>>(dst, cnt, NEDGES);
    scanA_kernel<<<NBLK, 1024>>>(cnt, rowptr, bsum, NNODES);
    scanB_kernel<<<1, 64>>>(bsum, NBLK);
    scanC_kernel<<<(NNODES + 255) / 256, 256>>>(cnt, rowptr, fill, bsum, NNODES);
    scatter_kernel<<<(NEDGES + 255) / 256, 256>>>(src, dst, fill, srcs, NEDGES);

    // ---- layer 1: 523 -> 256 (hd 64) ----
    {
        convertA0_kernel<<<NNODES, 256>>>(x0, abf);
        convertW1_kernel<<<256, 256>>>(W1, bbf, 256);
        dim3 grid(2, mtiles);
        hmma_gemm_kernel<<<grid, 256, GEMM_SMEM>>>(abf, bbf, wx, N, 256, KP1,
                                                   a1, 64, ssrc, sdst);
        gat_aggregate_ln_kernel<256, true><<<(N * 32 + 255) / 256, 256>>>(
            rowptr, srcs, ssrc, sdst, wx, g1, b1, nullptr, abf, N);
    }
    // ---- layer 2: 256 -> 256 (hd 64) ----
    {
        convertW_kernel<<<256, 256>>>(W2, bbf, 256);
        dim3 grid(2, mtiles);
        hmma_gemm_kernel<<<grid, 256, GEMM_SMEM>>>(abf, bbf, wx, N, 256, KP2,
                                                   a2, 64, ssrc, sdst);
        gat_aggregate_ln_kernel<256, true><<<(N * 32 + 255) / 256, 256>>>(
            rowptr, srcs, ssrc, sdst, wx, g2, b2, nullptr, abf, N);
    }
    // ---- layer 3: 256 -> 512 (hd 128), fp32 out ----
    {
        convertW_kernel<<<512, 256>>>(W3, bbf, 512);
        dim3 grid(4, mtiles);
        hmma_gemm_kernel<<<grid, 256, GEMM_SMEM>>>(abf, bbf, wx, N, 512, KP2,
                                                   a3, 128, ssrc, sdst);
        gat_aggregate_ln_kernel<512, false><<<(N * 32 + 255) / 256, 256>>>(
            rowptr, srcs, ssrc, sdst, wx, g3, b3, outf, nullptr, N);
    }
}

// round 15
// speedup vs baseline: 2.0055x; 1.0002x over previous
#include <cuda_runtime.h>
#include <cuda_bf16.h>
#include <math.h>
#include <stdint.h>

#define NNODES 50000
#define NEDGES 400000
#define HEADS  4
// Layer 1: K=523 -> section width 576 (9 tiles of 64); A'=[hi|lo] width 1152
#define SECW1 576
#define AW1   (2 * SECW1)     // 1152
// Layers 2/3: K=256 -> section width 256 (4 tiles); A'=[hi|lo] width 512
#define AW2   512
#define NBLK ((NNODES + 1023) / 1024)

// ---------------- scratch (device globals; no allocation allowed) -------------
__device__ float g_Wx  [NNODES * 512];
__device__ __nv_bfloat16 g_Abf[(size_t)NNODES * AW1];
__device__ __nv_bfloat16 g_Bbf[512 * AW1];
__device__ float g_ssrc[NNODES * HEADS];
__device__ float g_sdst[NNODES * HEADS];
__device__ int g_cnt   [NNODES];
__device__ int g_rowptr[NNODES + 1];
__device__ int g_fill  [NNODES];
__device__ int g_srcs  [NEDGES];
__device__ int g_bsum  [64];

// ============================ PTX helpers (sm_80-level only) ===================
__device__ __forceinline__ uint32_t smem_u32(const void* p) {
    uint32_t a;
    asm("{ .reg .u64 t; cvta.to.shared.u64 t, %1; cvt.u32.u64 %0, t; }" : "=r"(a) : "l"(p));
    return a;
}
__device__ __forceinline__ void ldsm_x4(uint32_t& r0, uint32_t& r1,
                                        uint32_t& r2, uint32_t& r3, uint32_t addr) {
    asm volatile("ldmatrix.sync.aligned.m8n8.x4.shared.b16 {%0,%1,%2,%3}, [%4];"
                 : "=r"(r0), "=r"(r1), "=r"(r2), "=r"(r3) : "r"(addr));
}
__device__ __forceinline__ void mma_bf16(float* c, const uint32_t* a, const uint32_t* b) {
    asm volatile("mma.sync.aligned.m16n8k16.row.col.f32.bf16.bf16.f32 "
                 "{%0,%1,%2,%3}, {%4,%5,%6,%7}, {%8,%9}, {%0,%1,%2,%3};"
                 : "+f"(c[0]), "+f"(c[1]), "+f"(c[2]), "+f"(c[3])
                 : "r"(a[0]), "r"(a[1]), "r"(a[2]), "r"(a[3]), "r"(b[0]), "r"(b[1]));
}
__device__ __forceinline__ void cp_async16(uint32_t smem_addr, const void* g, bool pred) {
    const int sz = pred ? 16 : 0;
    asm volatile("cp.async.cg.shared.global [%0], [%1], 16, %2;"
                 :: "r"(smem_addr), "l"(g), "r"(sz));
}
#define CP_ASYNC_COMMIT() asm volatile("cp.async.commit_group;" ::: "memory")
#define CP_ASYNC_WAIT0()  asm volatile("cp.async.wait_group 0;"  ::: "memory")

// === HMMA GEMM + fused attention scores =======================================
// Logical K' = 3 sections [A:hi|lo|hi] x [B:hi|hi|lo]; physical storage 2 sections.
// S = tiles (of 64) per section: logical ntiles = 3S, row width = 2S*64.
// aphys = t < 2S ? t : t-2S ;  bphys = t < S ? t : t-S.
#define ROWB 144
#define MATB (128 * ROWB)
#define BUFB (2 * MATB)
#define GEMM_SMEM (2 * BUFB)

__global__ __launch_bounds__(256, 2)
void hmma_gemm_kernel(const __nv_bfloat16* __restrict__ Aq,
                      const __nv_bfloat16* __restrict__ Bq,
                      float* __restrict__ C, int M, int N, int S,
                      const float* __restrict__ av, int hd,
                      float* __restrict__ ssrc, float* __restrict__ sdst)
{
    extern __shared__ __align__(16) char smem[];
    const uint32_t smem_base = smem_u32(smem);

    const int tid  = threadIdx.x;
    const int wid  = tid >> 5;
    const int lane = tid & 31;

    const int m0 = blockIdx.y * 128;
    const int n0 = blockIdx.x * 128;

    const int wm = (wid & 3) * 32;
    const int wn = (wid >> 2) * 64;

    const int lrow  = tid >> 1;
    const int lhalf = tid & 1;
    const bool a_ok = (m0 + lrow) < M;
    const int width = 2 * S * 64;                 // physical row width (elements)
    const __nv_bfloat16* Ag = Aq + (size_t)(a_ok ? (m0 + lrow) : 0) * width;
    const __nv_bfloat16* Bg = Bq + (size_t)(n0 + lrow) * width;

    const int sub = lane >> 3;
    const int srw = lane & 7;
    const uint32_t a_off = (uint32_t)(wm + (sub & 1) * 8 + srw) * ROWB + (sub >> 1) * 16;
    const uint32_t b_off = (uint32_t)(wn + (sub & 1) * 8 + srw) * ROWB + (sub >> 1) * 16;

    float acc[2][8][4];
#pragma unroll
    for (int i = 0; i < 2; i++)
#pragma unroll
        for (int j = 0; j < 8; j++)
#pragma unroll
            for (int r = 0; r < 4; r++) acc[i][j][r] = 0.f;

    const int ntiles = 3 * S;

    auto issue = [&](int t, int buf) {
        const int aphys = (t < 2 * S) ? t : t - 2 * S;
        const int bphys = (t < S) ? t : t - S;
        const uint32_t sa = smem_base + buf * BUFB;
        const uint32_t sb = sa + MATB;
        const size_t gofsA = (size_t)aphys * 64;
        const size_t gofsB = (size_t)bphys * 64;
#pragma unroll
        for (int q = 0; q < 4; q++) {
            const int c16 = lhalf * 4 + q;
            const uint32_t sofs = (uint32_t)lrow * ROWB + c16 * 16;
            cp_async16(sa + sofs, (const char*)(Ag + gofsA) + c16 * 16, a_ok);
            cp_async16(sb + sofs, (const char*)(Bg + gofsB) + c16 * 16, true);
        }
        CP_ASYNC_COMMIT();
    };

    issue(0, 0);
    CP_ASYNC_WAIT0();
    __syncthreads();

    int buf = 0;
    for (int t = 0; t < ntiles; t++) {
        const bool more = (t + 1) < ntiles;
        if (more) issue(t + 1, buf ^ 1);

        const uint32_t sa = smem_base + buf * BUFB;
        const uint32_t sb = sa + MATB;
#pragma unroll
        for (int k0 = 0; k0 < 64; k0 += 16) {
            uint32_t af[2][4];
#pragma unroll
            for (int mi = 0; mi < 2; mi++)
                ldsm_x4(af[mi][0], af[mi][1], af[mi][2], af[mi][3],
                        sa + a_off + mi * 16 * ROWB + k0 * 2);
            uint32_t bf[8][2];
#pragma unroll
            for (int np = 0; np < 4; np++) {
                uint32_t r0, r1, r2, r3;
                ldsm_x4(r0, r1, r2, r3, sb + b_off + np * 16 * ROWB + k0 * 2);
                bf[2 * np][0] = r0; bf[2 * np + 1][0] = r1;
                bf[2 * np][1] = r2; bf[2 * np + 1][1] = r3;
            }
#pragma unroll
            for (int mi = 0; mi < 2; mi++)
#pragma unroll
                for (int ni = 0; ni < 8; ni++)
                    mma_bf16(acc[mi][ni], af[mi], bf[ni]);
        }

        if (more) CP_ASYNC_WAIT0();
        __syncthreads();
        buf ^= 1;
    }

    const int gid = lane >> 2;
    const int tig = lane & 3;

    // ---- C store + fused per-head score partials ----
    const int cmask = hd - 1;
    float aS[4] = {0.f, 0.f, 0.f, 0.f};
    float aD[4] = {0.f, 0.f, 0.f, 0.f};

#pragma unroll
    for (int mi = 0; mi < 2; mi++) {
        const int m1 = m0 + wm + mi * 16 + gid;
        const int m2 = m1 + 8;
#pragma unroll
        for (int ni = 0; ni < 8; ni++) {
            const int nn = n0 + wn + ni * 8 + tig * 2;
            const int c  = nn & cmask;
            const float as0 = av[c], as1 = av[c + 1];
            const float ad0 = av[hd + c], ad1 = av[hd + c + 1];
            aS[mi * 2]     += acc[mi][ni][0] * as0 + acc[mi][ni][1] * as1;
            aD[mi * 2]     += acc[mi][ni][0] * ad0 + acc[mi][ni][1] * ad1;
            aS[mi * 2 + 1] += acc[mi][ni][2] * as0 + acc[mi][ni][3] * as1;
            aD[mi * 2 + 1] += acc[mi][ni][2] * ad0 + acc[mi][ni][3] * ad1;
            if (m1 < M) *(float2*)&C[(size_t)m1 * N + nn] =
                make_float2(acc[mi][ni][0], acc[mi][ni][1]);
            if (m2 < M) *(float2*)&C[(size_t)m2 * N + nn] =
                make_float2(acc[mi][ni][2], acc[mi][ni][3]);
        }
    }
#pragma unroll
    for (int r = 0; r < 4; r++) {
        aS[r] += __shfl_xor_sync(0xffffffffu, aS[r], 1);
        aS[r] += __shfl_xor_sync(0xffffffffu, aS[r], 2);
        aD[r] += __shfl_xor_sync(0xffffffffu, aD[r], 1);
        aD[r] += __shfl_xor_sync(0xffffffffu, aD[r], 2);
    }

    if (hd == 64) {
        const int head = (n0 + wn) / 64;
        if (tig == 0) {
#pragma unroll
            for (int mi = 0; mi < 2; mi++) {
                const int m1 = m0 + wm + mi * 16 + gid;
                const int m2 = m1 + 8;
                if (m1 < M) {
                    ssrc[m1 * 4 + head] = aS[mi * 2];
                    sdst[m1 * 4 + head] = aD[mi * 2];
                }
                if (m2 < M) {
                    ssrc[m2 * 4 + head] = aS[mi * 2 + 1];
                    sdst[m2 * 4 + head] = aD[mi * 2 + 1];
                }
            }
        }
    } else {
        // hd == 128: combine partials of warp pairs (wid, wid+4) via smem.
        float* sbuf = (float*)smem;
        __syncthreads();
        if (wid >= 4 && tig == 0) {
            const int base = (((wid & 3) * 8 + gid) * 4) * 2;
#pragma unroll
            for (int r = 0; r < 4; r++) {
                sbuf[base + r * 2]     = aS[r];
                sbuf[base + r * 2 + 1] = aD[r];
            }
        }
        __syncthreads();
        if (wid < 4 && tig == 0) {
            const int base = ((wid * 8 + gid) * 4) * 2;
#pragma unroll
            for (int r = 0; r < 4; r++) {
                aS[r] += sbuf[base + r * 2];
                aD[r] += sbuf[base + r * 2 + 1];
            }
            const int head = n0 / 128;
#pragma unroll
            for (int mi = 0; mi < 2; mi++) {
                const int m1 = m0 + wm + mi * 16 + gid;
                const int m2 = m1 + 8;
                if (m1 < M) {
                    ssrc[m1 * 4 + head] = aS[mi * 2];
                    sdst[m1 * 4 + head] = aD[mi * 2];
                }
                if (m2 < M) {
                    ssrc[m2 * 4 + head] = aS[mi * 2 + 1];
                    sdst[m2 * 4 + head] = aD[mi * 2 + 1];
                }
            }
        }
    }
}

// ====================== fp32 -> split bf16 conversions =========================
__device__ __forceinline__ void split_bf16(float x, __nv_bfloat16& hi, __nv_bfloat16& lo) {
    hi = __float2bfloat16(x);
    lo = __float2bfloat16(x - __bfloat162float(hi));
}
__device__ __forceinline__ uint32_t pack_bf2(__nv_bfloat16 a, __nv_bfloat16 b) {
    __nv_bfloat162 t = __halves2bfloat162(a, b);
    return *(uint32_t*)&t;
}

// A' layer 1: [hi | lo] at 0 / 576, width 1152; pads [523,576) per section zeroed.
// A rows only 4B-aligned (K=523 odd) -> scalar loads, packed u32 stores.
__global__ __launch_bounds__(256)
void convertA0_kernel(const float* __restrict__ x, __nv_bfloat16* __restrict__ out)
{
    const int m = blockIdx.x;
    const float* xr = x + (size_t)m * 523;
    __nv_bfloat16* orow = out + (size_t)m * AW1;
    uint32_t* o32 = (uint32_t*)orow;
    const int t = (int)threadIdx.x;
#pragma unroll
    for (int q = 0; q < 2; q++) {
        const int p = q * 256 + t;       // pair index, 261 pairs cover k=0..521
        if (p < 261) {
            const float x0 = xr[p * 2];
            const float x1 = xr[p * 2 + 1];
            __nv_bfloat16 h0, l0, h1, l1;
            split_bf16(x0, h0, l0);
            split_bf16(x1, h1, l1);
            o32[p]             = pack_bf2(h0, h1);
            o32[SECW1 / 2 + p] = pack_bf2(l0, l1);
        }
    }
    if (t == 0) {
        __nv_bfloat16 hi, lo;
        split_bf16(xr[522], hi, lo);
        orow[522]         = hi;
        orow[SECW1 + 522] = lo;
    }
    for (int j = 523 + t; j < SECW1; j += 256) {
        orow[j]         = __float2bfloat16(0.f);
        orow[SECW1 + j] = __float2bfloat16(0.f);
    }
}

// B' layer 1 from W[523,N]: [Bhi | Blo] at 0 / 576, width 1152, pads zeroed
__global__ __launch_bounds__(256)
void convertW1_kernel(const float* __restrict__ W, __nv_bfloat16* __restrict__ out, int N)
{
    const int n = blockIdx.x;
    __nv_bfloat16* orow = out + (size_t)n * AW1;
    for (int k = threadIdx.x; k < 523; k += 256) {
        __nv_bfloat16 hi, lo;
        split_bf16(W[(size_t)k * N + n], hi, lo);
        orow[k]         = hi;
        orow[SECW1 + k] = lo;
    }
    for (int j = 523 + threadIdx.x; j < SECW1; j += 256) {
        orow[j]         = __float2bfloat16(0.f);
        orow[SECW1 + j] = __float2bfloat16(0.f);
    }
}

// B' layers 2/3 from W[256,N]: [Bhi | Blo] at 0 / 256, width 512
__global__ __launch_bounds__(256)
void convertW_kernel(const float* __restrict__ W, __nv_bfloat16* __restrict__ out, int N)
{
    const int n = blockIdx.x;
    __nv_bfloat16* orow = out + (size_t)n * AW2;
    const int k = (int)threadIdx.x;
    __nv_bfloat16 hi, lo;
    split_bf16(W[(size_t)k * N + n], hi, lo);
    orow[k]       = hi;
    orow[256 + k] = lo;
}

// ---------------- CSR construction: parallel 3-phase scan ----------------------
__global__ void hist_kernel(const int* __restrict__ dst, int* __restrict__ cnt, int E)
{
    const int e = blockIdx.x * blockDim.x + threadIdx.x;
    if (e < E) atomicAdd(&cnt[dst[e]], 1);
}

__global__ __launch_bounds__(1024)
void scanA_kernel(const int* __restrict__ cnt, int* __restrict__ rowptr,
                  int* __restrict__ bsum, int n)
{
    __shared__ int sh[1024];
    const int i = blockIdx.x * 1024 + (int)threadIdx.x;
    const int v = (i < n) ? cnt[i] : 0;
    sh[threadIdx.x] = v;
    __syncthreads();
#pragma unroll
    for (int o = 1; o < 1024; o <<= 1) {
        const int t = (threadIdx.x >= (unsigned)o) ? sh[threadIdx.x - o] : 0;
        __syncthreads();
        sh[threadIdx.x] += t;
        __syncthreads();
    }
    if (i < n) rowptr[i + 1] = sh[threadIdx.x];
    if (threadIdx.x == 1023) bsum[blockIdx.x] = sh[1023];
}

__global__ __launch_bounds__(64)
void scanB_kernel(int* __restrict__ bsum, int nb)
{
    __shared__ int sh[64];
    const int t = (int)threadIdx.x;
    const int v = (t < nb) ? bsum[t] : 0;
    sh[t] = v;
    __syncthreads();
#pragma unroll
    for (int o = 1; o < 64; o <<= 1) {
        const int u = (t >= o) ? sh[t - o] : 0;
        __syncthreads();
        sh[t] += u;
        __syncthreads();
    }
    if (t < nb) bsum[t] = sh[t] - v;
}

__global__ void scanC_kernel(const int* __restrict__ cnt, int* __restrict__ rowptr,
                             int* __restrict__ fill, const int* __restrict__ bsum, int n)
{
    const int i = blockIdx.x * blockDim.x + threadIdx.x;
    if (i >= n) return;
    const int r = rowptr[i + 1] + bsum[i >> 10];
    rowptr[i + 1] = r;
    fill[i] = r - cnt[i];
    if (i == 0) rowptr[0] = 0;
}

__global__ void scatter_kernel(const int* __restrict__ src, const int* __restrict__ dst,
                               int* __restrict__ fill, int* __restrict__ srcs, int E)
{
    const int e = blockIdx.x * blockDim.x + threadIdx.x;
    if (e >= E) return;
    const int pos = atomicAdd(&fill[dst[e]], 1);
    srcs[pos] = src[e];
}

// ------ fused edge-softmax + aggregation + ELU + LayerNorm --------------------
template <int DOUT, bool OUT_BF16>
__global__ __launch_bounds__(256)
void gat_aggregate_ln_kernel(const int* __restrict__ rowptr,
                             const int* __restrict__ srcs,
                             const float* __restrict__ ssrc,
                             const float* __restrict__ sdst,
                             const float* __restrict__ Wx,
                             const float* __restrict__ g,
                             const float* __restrict__ b,
                             float* __restrict__ outf,
                             __nv_bfloat16* __restrict__ outb, int n)
{
    const int warp = (blockIdx.x * blockDim.x + threadIdx.x) >> 5;
    const int lane = threadIdx.x & 31;
    if (warp >= n) return;
    const int node = warp;
    const int begin = rowptr[node];
    const int end   = rowptr[node + 1];

    constexpr int PER = DOUT / 32;
    const int h = lane >> 3;

    const float4 sdv = *(const float4*)&sdst[node * 4];
    const float sd0 = sdv.x, sd1 = sdv.y, sd2 = sdv.z, sd3 = sdv.w;

    float d0 = 0.f, d1 = 0.f, d2 = 0.f, d3 = 0.f;
    for (int i = begin + lane; i < end; i += 32) {
        const int s = srcs[i];
        const float4 sv = *(const float4*)&ssrc[s * 4];
        float v;
        v = sv.x + sd0; v = v > 0.f ? v : 0.2f * v; d0 += __expf(v);
        v = sv.y + sd1; v = v > 0.f ? v : 0.2f * v; d1 += __expf(v);
        v = sv.z + sd2; v = v > 0.f ? v : 0.2f * v; d2 += __expf(v);
        v = sv.w + sd3; v = v > 0.f ? v : 0.2f * v; d3 += __expf(v);
    }
#pragma unroll
    for (int o = 16; o; o >>= 1) {
        d0 += __shfl_xor_sync(0xffffffffu, d0, o);
        d1 += __shfl_xor_sync(0xffffffffu, d1, o);
        d2 += __shfl_xor_sync(0xffffffffu, d2, o);
        d3 += __shfl_xor_sync(0xffffffffu, d3, o);
    }
    const float inv0 = 1.0f / (d0 + 1e-8f);
    const float inv1 = 1.0f / (d1 + 1e-8f);
    const float inv2 = 1.0f / (d2 + 1e-8f);
    const float inv3 = 1.0f / (d3 + 1e-8f);

    float acc[PER];
#pragma unroll
    for (int j = 0; j < PER; j++) acc[j] = 0.f;

    const int colbase = lane * PER;
    for (int i = begin; i < end; i++) {
        const int s = srcs[i];
        float al = 0.f;
        if (lane < 4) {
            const float sdh = (lane == 0) ? sd0 : (lane == 1) ? sd1
                            : (lane == 2) ? sd2 : sd3;
            const float ivh = (lane == 0) ? inv0 : (lane == 1) ? inv1
                            : (lane == 2) ? inv2 : inv3;
            float e = ssrc[s * 4 + lane] + sdh;
            e = e > 0.f ? e : 0.2f * e;
            al = __expf(e) * ivh;
        }
        const float alpha = __shfl_sync(0xffffffffu, al, h);
        const float4* w = (const float4*)&Wx[(long long)s * DOUT + colbase];
#pragma unroll
        for (int j = 0; j < PER / 4; j++) {
            const float4 wv = w[j];
            acc[j * 4 + 0] = fmaf(alpha, wv.x, acc[j * 4 + 0]);
            acc[j * 4 + 1] = fmaf(alpha, wv.y, acc[j * 4 + 1]);
            acc[j * 4 + 2] = fmaf(alpha, wv.z, acc[j * 4 + 2]);
            acc[j * 4 + 3] = fmaf(alpha, wv.w, acc[j * 4 + 3]);
        }
    }

    float sum = 0.f, sumsq = 0.f;
#pragma unroll
    for (int j = 0; j < PER; j++) {
        float v = acc[j];
        v = (v > 0.f) ? v : (__expf(v) - 1.0f);
        acc[j] = v;
        sum += v;
        sumsq = fmaf(v, v, sumsq);
    }
#pragma unroll
    for (int o = 16; o; o >>= 1) {
        sum   += __shfl_xor_sync(0xffffffffu, sum, o);
        sumsq += __shfl_xor_sync(0xffffffffu, sumsq, o);
    }
    const float inv = 1.0f / (float)DOUT;
    const float mu  = sum * inv;
    const float var = sumsq * inv - mu * mu;
    const float rs  = rsqrtf(var + 1e-5f);

    if (OUT_BF16) {
        union { __nv_bfloat16 b16[8]; uint4 v; } uhi, ulo;
#pragma unroll
        for (int j = 0; j < PER; j++) {
            const float fv = (acc[j] - mu) * rs * g[colbase + j] + b[colbase + j];
            split_bf16(fv, uhi.b16[j], ulo.b16[j]);
        }
        __nv_bfloat16* arow = outb + (size_t)node * (2 * DOUT);   // [hi | lo]
        *(uint4*)&arow[colbase]        = uhi.v;
        *(uint4*)&arow[DOUT + colbase] = ulo.v;
    } else {
        float* orow = &outf[(long long)node * DOUT + colbase];
#pragma unroll
        for (int j = 0; j < PER / 4; j++) {
            const float4 gv = *(const float4*)&g[colbase + j * 4];
            const float4 bv = *(const float4*)&b[colbase + j * 4];
            float4 ov;
            ov.x = (acc[j * 4 + 0] - mu) * rs * gv.x + bv.x;
            ov.y = (acc[j * 4 + 1] - mu) * rs * gv.y + bv.y;
            ov.z = (acc[j * 4 + 2] - mu) * rs * gv.z + bv.z;
            ov.w = (acc[j * 4 + 3] - mu) * rs * gv.w + bv.w;
            *(float4*)&orow[j * 4] = ov;
        }
    }
}

// ---------------- host orchestration ------------------------------------------
extern "C" void kernel_launch(void* const* d_in, const int* in_sizes, int n_in,
                              void* d_out, int out_size)
{
    const float* x0 = (const float*)d_in[0];
    const int*   ei = (const int*)d_in[1];
    const float* W1 = (const float*)d_in[2];
    const float* a1 = (const float*)d_in[3];
    const float* g1 = (const float*)d_in[4];
    const float* b1 = (const float*)d_in[5];
    const float* W2 = (const float*)d_in[6];
    const float* a2 = (const float*)d_in[7];
    const float* g2 = (const float*)d_in[8];
    const float* b2 = (const float*)d_in[9];
    const float* W3 = (const float*)d_in[10];
    const float* a3 = (const float*)d_in[11];
    const float* g3 = (const float*)d_in[12];
    const float* b3 = (const float*)d_in[13];

    const int* src = ei;
    const int* dst = ei + NEDGES;

    float *wx, *ssrc, *sdst;
    __nv_bfloat16 *abf, *bbf;
    int *cnt, *rowptr, *fill, *srcs, *bsum;
    cudaGetSymbolAddress((void**)&wx,     g_Wx);
    cudaGetSymbolAddress((void**)&abf,    g_Abf);
    cudaGetSymbolAddress((void**)&bbf,    g_Bbf);
    cudaGetSymbolAddress((void**)&ssrc,   g_ssrc);
    cudaGetSymbolAddress((void**)&sdst,   g_sdst);
    cudaGetSymbolAddress((void**)&cnt,    g_cnt);
    cudaGetSymbolAddress((void**)&rowptr, g_rowptr);
    cudaGetSymbolAddress((void**)&fill,   g_fill);
    cudaGetSymbolAddress((void**)&srcs,   g_srcs);
    cudaGetSymbolAddress((void**)&bsum,   g_bsum);

    cudaFuncSetAttribute(hmma_gemm_kernel,
                         cudaFuncAttributeMaxDynamicSharedMemorySize, GEMM_SMEM);

    float* outf = (float*)d_out;
    const int N = NNODES;
    const int mtiles = (N + 127) / 128;

    // Launch order puts gemm1 at slot 5 (profiler captures the 5th launch).
    cudaMemsetAsync(cnt, 0, NNODES * sizeof(int), 0);                 // 1
    convertA0_kernel<<<NNODES, 256>>>(x0, abf);                       // 2
    convertW1_kernel<<<256, 256>>>(W1, bbf, 256);                     // 3
    hist_kernel<<<(NEDGES + 255) / 256, 256>>>(dst, cnt, NEDGES);     // 4
    {
        dim3 grid(2, mtiles);
        hmma_gemm_kernel<<<grid, 256, GEMM_SMEM>>>(abf, bbf, wx, N, 256, 9,
                                                   a1, 64, ssrc, sdst);   // 5
    }
    scanA_kernel<<<NBLK, 1024>>>(cnt, rowptr, bsum, NNODES);
    scanB_kernel<<<1, 64>>>(bsum, NBLK);
    scanC_kernel<<<(NNODES + 255) / 256, 256>>>(cnt, rowptr, fill, bsum, NNODES);
    scatter_kernel<<<(NEDGES + 255) / 256, 256>>>(src, dst, fill, srcs, NEDGES);

    // ---- layer 1 aggregate ----
    gat_aggregate_ln_kernel<256, true><<<(N * 32 + 255) / 256, 256>>>(
        rowptr, srcs, ssrc, sdst, wx, g1, b1, nullptr, abf, N);

    // ---- layer 2: 256 -> 256 (hd 64) ----
    {
        convertW_kernel<<<256, 256>>>(W2, bbf, 256);
        dim3 grid(2, mtiles);
        hmma_gemm_kernel<<<grid, 256, GEMM_SMEM>>>(abf, bbf, wx, N, 256, 4,
                                                   a2, 64, ssrc, sdst);
        gat_aggregate_ln_kernel<256, true><<<(N * 32 + 255) / 256, 256>>>(
            rowptr, srcs, ssrc, sdst, wx, g2, b2, nullptr, abf, N);
    }
    // ---- layer 3: 256 -> 512 (hd 128), fp32 out ----
    {
        convertW_kernel<<<512, 256>>>(W3, bbf, 512);
        dim3 grid(4, mtiles);
        hmma_gemm_kernel<<<grid, 256, GEMM_SMEM>>>(abf, bbf, wx, N, 512, 4,
                                                   a3, 128, ssrc, sdst);
        gat_aggregate_ln_kernel<512, false><<<(N * 32 + 255) / 256, 256>>>(
            rowptr, srcs, ssrc, sdst, wx, g3, b3, outf, nullptr, N);
    }
}